// round 2
// baseline (speedup 1.0000x reference)
#include <cuda_runtime.h>
#include <math.h>

// ---------------- scratch (device globals; no allocations allowed) ----------------
// q1 buffer is reused as out_win scratch by K3/K4 (same size: 128*65536 == 256*128*256)
__device__ float g_q1[128u * 65536u];          // 32 MB : conv1 q output (NCHW), later out_win
__device__ float g_kv1[256u * 65536u];         // 64 MB : conv1 kv output (NCHW)
__device__ float g_qw[256u * 128u * 256u];     // 32 MB : q  in [win][c][m]
__device__ float g_kw[256u * 128u * 256u];     // 32 MB : k  in [win][c][m]
__device__ float g_vw[256u * 128u * 256u];     // 32 MB : v  in [win][c][m]

// =====================================================================================
// K1: per-pixel channel LayerNorm (C=32) + 1x1 convs -> q1[128][HW], kv1[256][HW]
//   grid 256 blocks x 256 threads, one pixel per thread. Weights staged in smem.
// =====================================================================================
__global__ void k1_ln_conv1(const float* __restrict__ lms, const float* __restrict__ pan,
                            const float* __restrict__ gms, const float* __restrict__ gpan,
                            const float* __restrict__ qw1, const float* __restrict__ qb1,
                            const float* __restrict__ kvw1, const float* __restrict__ kvb1)
{
    extern __shared__ float sw[];  // [0,4096): q_w1 (128x32)  [4096,4096+8192): kv_w1 (256x32)
    int t = threadIdx.x;
    for (int i = t; i < 128 * 32; i += 256) sw[i] = qw1[i];
    for (int i = t; i < 256 * 32; i += 256) sw[4096 + i] = kvw1[i];
    __syncthreads();

    int p = blockIdx.x * 256 + t;  // pixel index in [0, 65536)

    float xp[32], xl[32];
    float sp = 0.f, sp2 = 0.f, sl = 0.f, sl2 = 0.f;
#pragma unroll
    for (int i = 0; i < 32; i++) {
        float a = pan[i * 65536 + p]; xp[i] = a; sp += a; sp2 += a * a;
        float b = lms[i * 65536 + p]; xl[i] = b; sl += b; sl2 += b * b;
    }
    float mp = sp * (1.f / 32.f), vp = sp2 * (1.f / 32.f) - mp * mp;
    float ml = sl * (1.f / 32.f), vl = sl2 * (1.f / 32.f) - ml * ml;
    float rp = rsqrtf(vp + 1e-5f);
    float rl = rsqrtf(vl + 1e-5f);
#pragma unroll
    for (int i = 0; i < 32; i++) {
        xp[i] = (xp[i] - mp) * rp * gpan[i];
        xl[i] = (xl[i] - ml) * rl * gms[i];
    }

    const float4* wq  = (const float4*)sw;            // 128 rows x 8 float4
    const float4* wkv = (const float4*)(sw + 4096);   // 256 rows x 8 float4
    for (int o = 0; o < 128; o++) {
        float acc = qb1[o];
#pragma unroll
        for (int j = 0; j < 8; j++) {
            float4 w4 = wq[o * 8 + j];
            acc += w4.x * xp[4 * j] + w4.y * xp[4 * j + 1] + w4.z * xp[4 * j + 2] + w4.w * xp[4 * j + 3];
        }
        g_q1[o * 65536 + p] = acc;
    }
    for (int o = 0; o < 256; o++) {
        float acc = kvb1[o];
#pragma unroll
        for (int j = 0; j < 8; j++) {
            float4 w4 = wkv[o * 8 + j];
            acc += w4.x * xl[4 * j] + w4.y * xl[4 * j + 1] + w4.z * xl[4 * j + 2] + w4.w * xl[4 * j + 3];
        }
        g_kv1[o * 65536 + p] = acc;
    }
}

// =====================================================================================
// K2: depthwise 3x3 (SAME) + dilated-window scatter.
//   Window partition is DILATED: win = (h%16)*16 + (w%16), token m = (h/16)*16 + (w/16).
//   Block = (16-row slab h0=16*a, one channel). Stage 18x256 input rows in skewed smem
//   (conflict-free for the strided window-reads), write [win][c][m] fully coalesced.
//   grid (16, 384): channel c<128 -> q, 128..255 -> k, 256..383 -> v.
// =====================================================================================
#define SK18(r, c) ((r) * 272 + (c) + ((c) >> 4))

__global__ void k2_dwconv_scatter(const float* __restrict__ qw2, const float* __restrict__ qb2,
                                  const float* __restrict__ kvw2, const float* __restrict__ kvb2)
{
    __shared__ float s[18 * 272];
    int c = blockIdx.y;
    int a = blockIdx.x;
    int h0 = a * 16;
    int t = threadIdx.x;

    const float* src; float* dst; int dstc; const float* wsrc; const float* bsrc; int cw;
    if (c < 128)      { src = g_q1  + (size_t)c * 65536;         dst = g_qw; dstc = c;        wsrc = qw2;  bsrc = qb2;  cw = c; }
    else {
        int ck = c - 128;
        src = g_kv1 + (size_t)ck * 65536;
        wsrc = kvw2; bsrc = kvb2; cw = ck;
        if (ck < 128) { dst = g_kw; dstc = ck; }
        else          { dst = g_vw; dstc = ck - 128; }
    }

    float w9[9];
#pragma unroll
    for (int j = 0; j < 9; j++) w9[j] = wsrc[cw * 9 + j];
    float bias = bsrc[cw];

    // load 18 input rows (with h zero-padding)
    for (int i = t; i < 18 * 256; i += 256) {
        int rr = i >> 8, ww = i & 255;
        int h = h0 - 1 + rr;
        float v = (h >= 0 && h < 256) ? src[h * 256 + ww] : 0.f;
        s[SK18(rr, ww)] = v;
    }
    __syncthreads();

    int g = t >> 4, bcol = t & 15;   // lane group: 16 consecutive bcol -> 64B coalesced stores
    for (int j = 0; j < 16; j++) {
        int hh = j, wx = g;
        int wpix = bcol * 16 + wx;
        float acc = bias;
#pragma unroll
        for (int dy = 0; dy < 3; dy++) {
#pragma unroll
            for (int dx = 0; dx < 3; dx++) {
                int ww = wpix + dx - 1;
                float v = (ww >= 0 && ww < 256) ? s[SK18(hh + dy, ww)] : 0.f;
                acc += w9[dy * 3 + dx] * v;
            }
        }
        int win = hh * 16 + wx;
        dst[((size_t)win * 128 + dstc) * 256 + a * 16 + bcol] = acc;
    }
}

// =====================================================================================
// K3: attention. grid (4 m-slices, 8 heads, 256 windows), 256 threads.
//   Per block: 64 q-rows x all 256 keys. k-normalization (over tokens) folded into the
//   per-thread k registers. Logits tile kept in padded smem (pitch 260 -> conflict-free
//   for both row softmax and column AV). attn written coalesced over n. AV result goes
//   to out_win (reusing g_q1).
// =====================================================================================
__global__ void k3_attn(float* __restrict__ attn)
{
    extern __shared__ float sm[];
    float* L   = sm;                    // 64 x 260 logits / probs
    float* V   = sm + 16640;            // 16 x 260
    float* Q   = sm + 20800;            // 16 x 64   ([d][m])
    float* RED = sm + 21824;            // 16 x 8
    float* RN  = sm + 21952;            // 16

    int t    = threadIdx.x;
    int lane = t & 31, wid = t >> 5;
    int mq   = blockIdx.x;            // 0..3
    int head = blockIdx.y;            // 0..7
    int win  = blockIdx.z;            // 0..255
    int m0   = mq * 64;

    const float* qb = g_qw + ((size_t)win * 128 + head * 16) * 256;
    const float* kb = g_kw + ((size_t)win * 128 + head * 16) * 256;
    const float* vb = g_vw + ((size_t)win * 128 + head * 16) * 256;

    float k[16];
#pragma unroll
    for (int d = 0; d < 16; d++) k[d] = kb[d * 256 + t];

    for (int i = t; i < 1024; i += 256) {
        int d = i >> 6, m = i & 63;
        Q[d * 64 + m] = qb[d * 256 + m0 + m];
    }
#pragma unroll
    for (int d = 0; d < 16; d++) V[d * 260 + t] = vb[d * 256 + t];

    // ---- k norm over the 256 tokens, per channel d (fold 1/norm into k regs) ----
#pragma unroll
    for (int d = 0; d < 16; d++) {
        float ssq = k[d] * k[d];
#pragma unroll
        for (int off = 16; off > 0; off >>= 1) ssq += __shfl_xor_sync(0xFFFFFFFFu, ssq, off);
        if (lane == 0) RED[d * 8 + wid] = ssq;
    }
    __syncthreads();
    if (t < 16) {
        float s = 0.f;
#pragma unroll
        for (int j = 0; j < 8; j++) s += RED[t * 8 + j];
        RN[t] = 1.f / fmaxf(sqrtf(s), 1e-12f);
    }
    __syncthreads();
#pragma unroll
    for (int d = 0; d < 16; d++) k[d] *= RN[d];

    // ---- QK: thread owns column n=t, computes 64 logits ----
    for (int m = 0; m < 64; m += 4) {
        float a0 = 0.f, a1 = 0.f, a2 = 0.f, a3 = 0.f;
#pragma unroll
        for (int d = 0; d < 16; d++) {
            float4 q4 = *(const float4*)&Q[d * 64 + m];
            a0 += q4.x * k[d]; a1 += q4.y * k[d]; a2 += q4.z * k[d]; a3 += q4.w * k[d];
        }
        L[(m + 0) * 260 + t] = a0;
        L[(m + 1) * 260 + t] = a1;
        L[(m + 2) * 260 + t] = a2;
        L[(m + 3) * 260 + t] = a3;
    }
    __syncthreads();

    // ---- softmax: warp per row (8 rows each), write attn coalesced ----
    for (int r = 0; r < 8; r++) {
        int m = wid * 8 + r;
        float v8[8];
        float mx = -3.0e38f;
#pragma unroll
        for (int j = 0; j < 8; j++) { v8[j] = L[m * 260 + lane + 32 * j]; mx = fmaxf(mx, v8[j]); }
#pragma unroll
        for (int off = 16; off > 0; off >>= 1) mx = fmaxf(mx, __shfl_xor_sync(0xFFFFFFFFu, mx, off));
        float s = 0.f;
#pragma unroll
        for (int j = 0; j < 8; j++) { v8[j] = expf(v8[j] - mx); s += v8[j]; }
#pragma unroll
        for (int off = 16; off > 0; off >>= 1) s += __shfl_xor_sync(0xFFFFFFFFu, s, off);
        float rinv = 1.f / s;
        float* orow = attn + ((size_t)((win * 8 + head) * 256 + m0 + m)) * 256;
#pragma unroll
        for (int j = 0; j < 8; j++) {
            float pval = v8[j] * rinv;
            L[m * 260 + lane + 32 * j] = pval;
            orow[lane + 32 * j] = pval;
        }
    }
    __syncthreads();

    // ---- AV: thread owns (m = t/4, d-group = t%4 -> 4 channels), stream n ----
    {
        int m = t >> 2, dg = t & 3;
        float acc[4] = {0.f, 0.f, 0.f, 0.f};
        for (int n = 0; n < 256; n += 4) {
            float4 lp = *(const float4*)&L[m * 260 + n];
#pragma unroll
            for (int i = 0; i < 4; i++) {
                float4 vv = *(const float4*)&V[(dg * 4 + i) * 260 + n];
                acc[i] += lp.x * vv.x + lp.y * vv.y + lp.z * vv.z + lp.w * vv.w;
            }
        }
        float* outw = g_q1;  // reuse as out_win [win][c][m]
#pragma unroll
        for (int i = 0; i < 4; i++) {
            outw[((size_t)win * 128 + head * 16 + dg * 4 + i) * 256 + m0 + m] = acc[i];
        }
    }
}

// =====================================================================================
// K4: window reverse for `out`: out_win [win][c][m] -> NCHW, via skewed-smem transpose.
//   grid (16 slabs, 128 channels), 256 threads.
// =====================================================================================
__global__ void k4_winrev(float* __restrict__ outp)
{
    __shared__ float s[16 * 272];
    int a = blockIdx.x;     // slab: rows h = a*16 + wy
    int c = blockIdx.y;
    int t = threadIdx.x;
    int g = t >> 4, bcol = t & 15;

    const float* outw = g_q1;
    for (int j = 0; j < 16; j++) {
        // wy = j, wx = g, b = bcol  -> pixel (a*16+wy, b*16+wx)
        float v = outw[((size_t)(j * 16 + g) * 128 + c) * 256 + a * 16 + bcol];
        int col = bcol * 16 + g;
        s[j * 272 + col + (col >> 4)] = v;
    }
    __syncthreads();
    for (int j = 0; j < 16; j++) {
        int col = t;
        outp[(size_t)c * 65536 + (a * 16 + j) * 256 + t] = s[j * 272 + col + (col >> 4)];
    }
}

// =====================================================================================
extern "C" void kernel_launch(void* const* d_in, const int* in_sizes, int n_in,
                              void* d_out, int out_size)
{
    const float* lms   = (const float*)d_in[0];
    const float* pan   = (const float*)d_in[1];
    const float* gms   = (const float*)d_in[2];
    const float* gpan  = (const float*)d_in[3];
    const float* qw1   = (const float*)d_in[4];
    const float* qb1   = (const float*)d_in[5];
    const float* qw2   = (const float*)d_in[6];
    const float* qb2   = (const float*)d_in[7];
    const float* kvw1  = (const float*)d_in[8];
    const float* kvb1  = (const float*)d_in[9];
    const float* kvw2  = (const float*)d_in[10];
    const float* kvb2  = (const float*)d_in[11];

    float* attn = (float*)d_out;                   // (256, 8, 256, 256)
    float* outp = attn + 134217728;                // (1, 128, 256, 256)

    cudaFuncSetAttribute(k3_attn, cudaFuncAttributeMaxDynamicSharedMemorySize, 90112);

    k1_ln_conv1<<<256, 256, 49152>>>(lms, pan, gms, gpan, qw1, qb1, kvw1, kvb1);
    k2_dwconv_scatter<<<dim3(16, 384), 256>>>(qw2, qb2, kvw2, kvb2);
    k3_attn<<<dim3(4, 8, 256), 256, 87872>>>(attn);
    k4_winrev<<<dim3(16, 128), 256>>>(outp);
}

// round 4
// speedup vs baseline: 1.2958x; 1.2958x over previous
#include <cuda_runtime.h>
#include <math.h>

// ---------------- scratch (device globals; no allocations allowed) ----------------
__device__ float g_q1[128u * 65536u];          // 32 MB : conv1 q output (NCHW), later out_win
__device__ float g_kv1[256u * 65536u];         // 64 MB : conv1 kv output (NCHW)
__device__ float g_qw[256u * 128u * 256u];     // 32 MB : q  in [win][c][m]
__device__ float g_kw[256u * 128u * 256u];     // 32 MB : k  in [win][c][m]
__device__ float g_vw[256u * 128u * 256u];     // 32 MB : v  in [win][c][m]

// =====================================================================================
// helpers
// =====================================================================================
__device__ __forceinline__ unsigned f2tf32(float f) {
    unsigned u;
    asm("cvt.rna.tf32.f32 %0, %1;" : "=r"(u) : "f"(f));
    return u;
}
__device__ __forceinline__ void mma_tf32(float c[4], const unsigned a[4], const unsigned b[2]) {
    asm volatile(
        "mma.sync.aligned.m16n8k8.row.col.f32.tf32.tf32.f32 "
        "{%0,%1,%2,%3},{%4,%5,%6,%7},{%8,%9},{%0,%1,%2,%3};"
        : "+f"(c[0]), "+f"(c[1]), "+f"(c[2]), "+f"(c[3])
        : "r"(a[0]), "r"(a[1]), "r"(a[2]), "r"(a[3]), "r"(b[0]), "r"(b[1]));
}

// =====================================================================================
// K1: per-pixel channel LayerNorm (C=32) + 1x1 convs -> q1[128][HW], kv1[256][HW]
// =====================================================================================
__global__ void k1_ln_conv1(const float* __restrict__ lms, const float* __restrict__ pan,
                            const float* __restrict__ gms, const float* __restrict__ gpan,
                            const float* __restrict__ qw1, const float* __restrict__ qb1,
                            const float* __restrict__ kvw1, const float* __restrict__ kvb1)
{
    extern __shared__ float sw[];  // [0,4096): q_w1 (128x32)  [4096,12288): kv_w1 (256x32)
    int t = threadIdx.x;
    for (int i = t; i < 128 * 32; i += 256) sw[i] = qw1[i];
    for (int i = t; i < 256 * 32; i += 256) sw[4096 + i] = kvw1[i];
    __syncthreads();

    int p = blockIdx.x * 256 + t;

    float xp[32], xl[32];
    float sp = 0.f, sp2 = 0.f, sl = 0.f, sl2 = 0.f;
#pragma unroll
    for (int i = 0; i < 32; i++) {
        float a = pan[i * 65536 + p]; xp[i] = a; sp += a; sp2 += a * a;
        float b = lms[i * 65536 + p]; xl[i] = b; sl += b; sl2 += b * b;
    }
    float mp = sp * (1.f / 32.f), vp = sp2 * (1.f / 32.f) - mp * mp;
    float ml = sl * (1.f / 32.f), vl = sl2 * (1.f / 32.f) - ml * ml;
    float rp = rsqrtf(vp + 1e-5f);
    float rl = rsqrtf(vl + 1e-5f);
#pragma unroll
    for (int i = 0; i < 32; i++) {
        xp[i] = (xp[i] - mp) * rp * gpan[i];
        xl[i] = (xl[i] - ml) * rl * gms[i];
    }

    const float4* wq  = (const float4*)sw;
    const float4* wkv = (const float4*)(sw + 4096);
    for (int o = 0; o < 128; o += 2) {   // dual accumulators for ILP
        float acc0 = qb1[o], acc1 = qb1[o + 1];
#pragma unroll
        for (int j = 0; j < 8; j++) {
            float4 w0 = wq[o * 8 + j];
            float4 w1 = wq[(o + 1) * 8 + j];
            acc0 += w0.x * xp[4 * j] + w0.y * xp[4 * j + 1] + w0.z * xp[4 * j + 2] + w0.w * xp[4 * j + 3];
            acc1 += w1.x * xp[4 * j] + w1.y * xp[4 * j + 1] + w1.z * xp[4 * j + 2] + w1.w * xp[4 * j + 3];
        }
        g_q1[o * 65536 + p] = acc0;
        g_q1[(o + 1) * 65536 + p] = acc1;
    }
    for (int o = 0; o < 256; o += 2) {
        float acc0 = kvb1[o], acc1 = kvb1[o + 1];
#pragma unroll
        for (int j = 0; j < 8; j++) {
            float4 w0 = wkv[o * 8 + j];
            float4 w1 = wkv[(o + 1) * 8 + j];
            acc0 += w0.x * xl[4 * j] + w0.y * xl[4 * j + 1] + w0.z * xl[4 * j + 2] + w0.w * xl[4 * j + 3];
            acc1 += w1.x * xl[4 * j] + w1.y * xl[4 * j + 1] + w1.z * xl[4 * j + 2] + w1.w * xl[4 * j + 3];
        }
        g_kv1[o * 65536 + p] = acc0;
        g_kv1[(o + 1) * 65536 + p] = acc1;
    }
}

// =====================================================================================
// K2: depthwise 3x3 (SAME) + dilated-window scatter.
// =====================================================================================
#define SK18(r, c) ((r) * 272 + (c) + ((c) >> 4))

__global__ void k2_dwconv_scatter(const float* __restrict__ qw2, const float* __restrict__ qb2,
                                  const float* __restrict__ kvw2, const float* __restrict__ kvb2)
{
    __shared__ float s[18 * 272];
    int c = blockIdx.y;
    int a = blockIdx.x;
    int h0 = a * 16;
    int t = threadIdx.x;

    const float* src; float* dst; int dstc; const float* wsrc; const float* bsrc; int cw;
    if (c < 128)      { src = g_q1  + (size_t)c * 65536;         dst = g_qw; dstc = c;        wsrc = qw2;  bsrc = qb2;  cw = c; }
    else {
        int ck = c - 128;
        src = g_kv1 + (size_t)ck * 65536;
        wsrc = kvw2; bsrc = kvb2; cw = ck;
        if (ck < 128) { dst = g_kw; dstc = ck; }
        else          { dst = g_vw; dstc = ck - 128; }
    }

    float w9[9];
#pragma unroll
    for (int j = 0; j < 9; j++) w9[j] = wsrc[cw * 9 + j];
    float bias = bsrc[cw];

    for (int i = t; i < 18 * 256; i += 256) {
        int rr = i >> 8, ww = i & 255;
        int h = h0 - 1 + rr;
        float v = (h >= 0 && h < 256) ? src[h * 256 + ww] : 0.f;
        s[SK18(rr, ww)] = v;
    }
    __syncthreads();

    int g = t >> 4, bcol = t & 15;
    for (int j = 0; j < 16; j++) {
        int hh = j, wx = g;
        int wpix = bcol * 16 + wx;
        float acc = bias;
#pragma unroll
        for (int dy = 0; dy < 3; dy++) {
#pragma unroll
            for (int dx = 0; dx < 3; dx++) {
                int ww = wpix + dx - 1;
                float v = (ww >= 0 && ww < 256) ? s[SK18(hh + dy, ww)] : 0.f;
                acc += w9[dy * 3 + dx] * v;
            }
        }
        int win = hh * 16 + wx;
        dst[((size_t)win * 128 + dstc) * 256 + a * 16 + bcol] = acc;
    }
}

// =====================================================================================
// K3: attention via tf32 tensor-core mma.
//   grid (8 m-slices of 32 rows, 8 heads, 256 windows), 256 threads (8 warps).
//   smem 76.8 KB -> up to 3 CTAs/SM.
// =====================================================================================
__global__ void k3_attn_mma(float* __restrict__ attn)
{
    extern __shared__ float sm[];
    float* S  = sm;                      // 8448
    float* Ks = sm + 8448;               // 4224
    float* Vs = sm + 12672;              // 4224
    float* U  = sm + 16896;              // 2304 union
    float* Qs  = U;                      // 640  (32 x 20)
    float* RED = U + 640;                // 128
    float* RN  = U + 768;                // 16
    float* Os  = U;                      // 2304 (4 x 32 x 18), reuses Qs after QK

    unsigned* Su = (unsigned*)S;
    unsigned* Ku = (unsigned*)Ks;
    unsigned* Vu = (unsigned*)Vs;
    unsigned* Qu = (unsigned*)Qs;

    int t    = threadIdx.x;
    int lane = t & 31, wid = t >> 5;
    int g    = lane >> 2, tig = lane & 3;     // mma fragment coords
    int mq   = blockIdx.x;                    // 0..7  (32-row slice)
    int head = blockIdx.y;
    int win  = blockIdx.z;
    int m0   = mq * 32;

    const float* qb = g_qw + ((size_t)win * 128 + head * 16) * 256;
    const float* kb = g_kw + ((size_t)win * 128 + head * 16) * 256;
    const float* vb = g_vw + ((size_t)win * 128 + head * 16) * 256;

    // ---- stage K (regs), V (tf32 smem), Q (tf32 smem) ----
    float k[16];
#pragma unroll
    for (int d = 0; d < 16; d++) k[d] = kb[d * 256 + t];
#pragma unroll
    for (int d = 0; d < 16; d++) Vu[d * 264 + t] = f2tf32(vb[d * 256 + t]);
#pragma unroll
    for (int i = 0; i < 2; i++) {
        int idx = i * 256 + t;
        int m = idx & 31, d = idx >> 5;
        Qu[m * 20 + d] = f2tf32(qb[d * 256 + m0 + m]);
    }

    // ---- k norm over tokens per channel d ----
#pragma unroll
    for (int d = 0; d < 16; d++) {
        float ssq = k[d] * k[d];
#pragma unroll
        for (int off = 16; off > 0; off >>= 1) ssq += __shfl_xor_sync(0xFFFFFFFFu, ssq, off);
        if (lane == 0) RED[d * 8 + wid] = ssq;
    }
    __syncthreads();
    if (t < 16) {
        float s = 0.f;
#pragma unroll
        for (int j = 0; j < 8; j++) s += RED[t * 8 + j];
        RN[t] = 1.f / fmaxf(sqrtf(s), 1e-12f);
    }
    __syncthreads();
#pragma unroll
    for (int d = 0; d < 16; d++) Ku[d * 264 + t] = f2tf32(k[d] * RN[d]);
    __syncthreads();

    // ---- QK: warp = (mt in 0..1) x (nq in 0..3); tile m16 x n64, K=16 ----
    {
        int mt = wid >> 2, nq = wid & 3;
        int mrow = mt * 16;
        unsigned a[2][4];
#pragma unroll
        for (int ks = 0; ks < 2; ks++) {
            int k0 = ks * 8;
            a[ks][0] = Qu[(mrow + g) * 20 + k0 + tig];
            a[ks][1] = Qu[(mrow + 8 + g) * 20 + k0 + tig];
            a[ks][2] = Qu[(mrow + g) * 20 + k0 + tig + 4];
            a[ks][3] = Qu[(mrow + 8 + g) * 20 + k0 + tig + 4];
        }
#pragma unroll
        for (int nt = 0; nt < 8; nt++) {
            int n0 = nq * 64 + nt * 8;
            float c[4] = {0.f, 0.f, 0.f, 0.f};
#pragma unroll
            for (int ks = 0; ks < 2; ks++) {
                int k0 = ks * 8;
                unsigned b[2] = { Ku[(k0 + tig) * 264 + n0 + g],
                                  Ku[(k0 + tig + 4) * 264 + n0 + g] };
                mma_tf32(c, a[ks], b);
            }
            *(float2*)&S[(mrow + g) * 264 + n0 + tig * 2]     = make_float2(c[0], c[1]);
            *(float2*)&S[(mrow + 8 + g) * 264 + n0 + tig * 2] = make_float2(c[2], c[3]);
        }
    }
    __syncthreads();

    // ---- softmax: warp handles 4 rows; write attn (fp32) + probs (tf32 to S) ----
#pragma unroll
    for (int r = 0; r < 4; r++) {
        int m = wid * 4 + r;
        float v8[8];
        float mx = -3.0e38f;
#pragma unroll
        for (int j = 0; j < 8; j++) { v8[j] = S[m * 264 + lane + 32 * j]; mx = fmaxf(mx, v8[j]); }
#pragma unroll
        for (int off = 16; off > 0; off >>= 1) mx = fmaxf(mx, __shfl_xor_sync(0xFFFFFFFFu, mx, off));
        float s = 0.f;
#pragma unroll
        for (int j = 0; j < 8; j++) { v8[j] = __expf(v8[j] - mx); s += v8[j]; }
#pragma unroll
        for (int off = 16; off > 0; off >>= 1) s += __shfl_xor_sync(0xFFFFFFFFu, s, off);
        float rinv = 1.f / s;
        float* orow = attn + ((size_t)((win * 8 + head) * 256 + m0 + m)) * 256;
#pragma unroll
        for (int j = 0; j < 8; j++) {
            float p = v8[j] * rinv;
            orow[lane + 32 * j] = p;
            Su[m * 264 + lane + 32 * j] = f2tf32(p);
        }
    }
    __syncthreads();

    // ---- AV: O[m][d] = sum_n P[m][n] V[d][n]. warp = (kq in 0..3) x (mt in 0..1). ----
    {
        int kq = wid >> 1, mt = wid & 1;
        int mrow = mt * 16;
        float c0[4] = {0.f, 0.f, 0.f, 0.f};   // d 0..7
        float c1[4] = {0.f, 0.f, 0.f, 0.f};   // d 8..15
#pragma unroll
        for (int ks = 0; ks < 8; ks++) {
            int k0 = kq * 64 + ks * 8;
            unsigned a[4] = { Su[(mrow + g) * 264 + k0 + tig],
                              Su[(mrow + 8 + g) * 264 + k0 + tig],
                              Su[(mrow + g) * 264 + k0 + tig + 4],
                              Su[(mrow + 8 + g) * 264 + k0 + tig + 4] };
            unsigned b0[2] = { Vu[g * 264 + k0 + tig], Vu[g * 264 + k0 + tig + 4] };
            mma_tf32(c0, a, b0);
            unsigned b1[2] = { Vu[(8 + g) * 264 + k0 + tig], Vu[(8 + g) * 264 + k0 + tig + 4] };
            mma_tf32(c1, a, b1);
        }
        *(float2*)&Os[(kq * 32 + mrow + g) * 18 + tig * 2]         = make_float2(c0[0], c0[1]);
        *(float2*)&Os[(kq * 32 + mrow + 8 + g) * 18 + tig * 2]     = make_float2(c0[2], c0[3]);
        *(float2*)&Os[(kq * 32 + mrow + g) * 18 + 8 + tig * 2]     = make_float2(c1[0], c1[1]);
        *(float2*)&Os[(kq * 32 + mrow + 8 + g) * 18 + 8 + tig * 2] = make_float2(c1[2], c1[3]);
    }
    __syncthreads();

    // ---- reduce k-quarters and write out_win [win][c][m] coalesced ----
    float* outw = g_q1;
#pragma unroll
    for (int i = 0; i < 2; i++) {
        int idx = i * 256 + t;
        int m = idx & 31, d = idx >> 5;
        float s = Os[(0 * 32 + m) * 18 + d] + Os[(1 * 32 + m) * 18 + d]
                + Os[(2 * 32 + m) * 18 + d] + Os[(3 * 32 + m) * 18 + d];
        outw[((size_t)win * 128 + head * 16 + d) * 256 + m0 + m] = s;
    }
}

// =====================================================================================
// K4: window reverse for `out`: out_win [win][c][m] -> NCHW
// =====================================================================================
__global__ void k4_winrev(float* __restrict__ outp)
{
    __shared__ float s[16 * 272];
    int a = blockIdx.x;
    int c = blockIdx.y;
    int t = threadIdx.x;
    int g = t >> 4, bcol = t & 15;

    const float* outw = g_q1;
    for (int j = 0; j < 16; j++) {
        float v = outw[((size_t)(j * 16 + g) * 128 + c) * 256 + a * 16 + bcol];
        int col = bcol * 16 + g;
        s[j * 272 + col + (col >> 4)] = v;
    }
    __syncthreads();
    for (int j = 0; j < 16; j++) {
        int col = t;
        outp[(size_t)c * 65536 + (a * 16 + j) * 256 + t] = s[j * 272 + col + (col >> 4)];
    }
}

// =====================================================================================
extern "C" void kernel_launch(void* const* d_in, const int* in_sizes, int n_in,
                              void* d_out, int out_size)
{
    const float* lms   = (const float*)d_in[0];
    const float* pan   = (const float*)d_in[1];
    const float* gms   = (const float*)d_in[2];
    const float* gpan  = (const float*)d_in[3];
    const float* qw1   = (const float*)d_in[4];
    const float* qb1   = (const float*)d_in[5];
    const float* qw2   = (const float*)d_in[6];
    const float* qb2   = (const float*)d_in[7];
    const float* kvw1  = (const float*)d_in[8];
    const float* kvb1  = (const float*)d_in[9];
    const float* kvw2  = (const float*)d_in[10];
    const float* kvb2  = (const float*)d_in[11];

    float* attn = (float*)d_out;                   // (256, 8, 256, 256)
    float* outp = attn + 134217728;                // (1, 128, 256, 256)

    cudaFuncSetAttribute(k3_attn_mma, cudaFuncAttributeMaxDynamicSharedMemorySize, 76800);

    k1_ln_conv1<<<256, 256, 49152>>>(lms, pan, gms, gpan, qw1, qb1, kvw1, kvb1);
    k2_dwconv_scatter<<<dim3(16, 384), 256>>>(qw2, qb2, kvw2, kvb2);
    k3_attn_mma<<<dim3(8, 8, 256), 256, 76800>>>(attn);
    k4_winrev<<<dim3(16, 128), 256>>>(outp);
}

// round 5
// speedup vs baseline: 2.0016x; 1.5447x over previous
#include <cuda_runtime.h>
#include <math.h>

// ---------------- scratch (device globals; no allocations allowed) ----------------
__device__ float g_q1[128u * 65536u];          // 32 MB : conv1 q output (NCHW), later out_win
__device__ float g_kv1[256u * 65536u];         // 64 MB : conv1 kv output (NCHW)
__device__ float g_qw[256u * 128u * 256u];     // 32 MB : q  in [win][c][m]
__device__ float g_kw[256u * 128u * 256u];     // 32 MB : k  in [win][c][m]
__device__ float g_vw[256u * 128u * 256u];     // 32 MB : v  in [win][c][m]

// =====================================================================================
// helpers
// =====================================================================================
__device__ __forceinline__ unsigned f2tf32(float f) {
    unsigned u;
    asm("cvt.rna.tf32.f32 %0, %1;" : "=r"(u) : "f"(f));
    return u;
}
__device__ __forceinline__ void mma_tf32(float c[4], const unsigned a[4], const unsigned b[2]) {
    asm volatile(
        "mma.sync.aligned.m16n8k8.row.col.f32.tf32.tf32.f32 "
        "{%0,%1,%2,%3},{%4,%5,%6,%7},{%8,%9},{%0,%1,%2,%3};"
        : "+f"(c[0]), "+f"(c[1]), "+f"(c[2]), "+f"(c[3])
        : "r"(a[0]), "r"(a[1]), "r"(a[2]), "r"(a[3]), "r"(b[0]), "r"(b[1]));
}

// =====================================================================================
// K1: per-pixel channel LayerNorm (C=32) + 1x1 convs -> q1[128][HW], kv1[256][HW]
// =====================================================================================
__global__ void k1_ln_conv1(const float* __restrict__ lms, const float* __restrict__ pan,
                            const float* __restrict__ gms, const float* __restrict__ gpan,
                            const float* __restrict__ qw1, const float* __restrict__ qb1,
                            const float* __restrict__ kvw1, const float* __restrict__ kvb1)
{
    extern __shared__ float sw[];
    int t = threadIdx.x;
    for (int i = t; i < 128 * 32; i += 256) sw[i] = qw1[i];
    for (int i = t; i < 256 * 32; i += 256) sw[4096 + i] = kvw1[i];
    __syncthreads();

    int p = blockIdx.x * 256 + t;

    float xp[32], xl[32];
    float sp = 0.f, sp2 = 0.f, sl = 0.f, sl2 = 0.f;
#pragma unroll
    for (int i = 0; i < 32; i++) {
        float a = pan[i * 65536 + p]; xp[i] = a; sp += a; sp2 += a * a;
        float b = lms[i * 65536 + p]; xl[i] = b; sl += b; sl2 += b * b;
    }
    float mp = sp * (1.f / 32.f), vp = sp2 * (1.f / 32.f) - mp * mp;
    float ml = sl * (1.f / 32.f), vl = sl2 * (1.f / 32.f) - ml * ml;
    float rp = rsqrtf(vp + 1e-5f);
    float rl = rsqrtf(vl + 1e-5f);
#pragma unroll
    for (int i = 0; i < 32; i++) {
        xp[i] = (xp[i] - mp) * rp * gpan[i];
        xl[i] = (xl[i] - ml) * rl * gms[i];
    }

    const float4* wq  = (const float4*)sw;
    const float4* wkv = (const float4*)(sw + 4096);
    for (int o = 0; o < 128; o += 2) {
        float acc0 = qb1[o], acc1 = qb1[o + 1];
#pragma unroll
        for (int j = 0; j < 8; j++) {
            float4 w0 = wq[o * 8 + j];
            float4 w1 = wq[(o + 1) * 8 + j];
            acc0 += w0.x * xp[4 * j] + w0.y * xp[4 * j + 1] + w0.z * xp[4 * j + 2] + w0.w * xp[4 * j + 3];
            acc1 += w1.x * xp[4 * j] + w1.y * xp[4 * j + 1] + w1.z * xp[4 * j + 2] + w1.w * xp[4 * j + 3];
        }
        g_q1[o * 65536 + p] = acc0;
        g_q1[(o + 1) * 65536 + p] = acc1;
    }
    for (int o = 0; o < 256; o += 2) {
        float acc0 = kvb1[o], acc1 = kvb1[o + 1];
#pragma unroll
        for (int j = 0; j < 8; j++) {
            float4 w0 = wkv[o * 8 + j];
            float4 w1 = wkv[(o + 1) * 8 + j];
            acc0 += w0.x * xl[4 * j] + w0.y * xl[4 * j + 1] + w0.z * xl[4 * j + 2] + w0.w * xl[4 * j + 3];
            acc1 += w1.x * xl[4 * j] + w1.y * xl[4 * j + 1] + w1.z * xl[4 * j + 2] + w1.w * xl[4 * j + 3];
        }
        g_kv1[o * 65536 + p] = acc0;
        g_kv1[(o + 1) * 65536 + p] = acc1;
    }
}

// =====================================================================================
// K2: depthwise 3x3 (SAME) + dilated-window scatter.
// =====================================================================================
#define SK18(r, c) ((r) * 272 + (c) + ((c) >> 4))

__global__ void k2_dwconv_scatter(const float* __restrict__ qw2, const float* __restrict__ qb2,
                                  const float* __restrict__ kvw2, const float* __restrict__ kvb2)
{
    __shared__ float s[18 * 272];
    int c = blockIdx.y;
    int a = blockIdx.x;
    int h0 = a * 16;
    int t = threadIdx.x;

    const float* src; float* dst; int dstc; const float* wsrc; const float* bsrc; int cw;
    if (c < 128)      { src = g_q1  + (size_t)c * 65536;         dst = g_qw; dstc = c;        wsrc = qw2;  bsrc = qb2;  cw = c; }
    else {
        int ck = c - 128;
        src = g_kv1 + (size_t)ck * 65536;
        wsrc = kvw2; bsrc = kvb2; cw = ck;
        if (ck < 128) { dst = g_kw; dstc = ck; }
        else          { dst = g_vw; dstc = ck - 128; }
    }

    float w9[9];
#pragma unroll
    for (int j = 0; j < 9; j++) w9[j] = wsrc[cw * 9 + j];
    float bias = bsrc[cw];

    for (int i = t; i < 18 * 256; i += 256) {
        int rr = i >> 8, ww = i & 255;
        int h = h0 - 1 + rr;
        float v = (h >= 0 && h < 256) ? src[h * 256 + ww] : 0.f;
        s[SK18(rr, ww)] = v;
    }
    __syncthreads();

    int g = t >> 4, bcol = t & 15;
    for (int j = 0; j < 16; j++) {
        int hh = j, wx = g;
        int wpix = bcol * 16 + wx;
        float acc = bias;
#pragma unroll
        for (int dy = 0; dy < 3; dy++) {
#pragma unroll
            for (int dx = 0; dx < 3; dx++) {
                int ww = wpix + dx - 1;
                float v = (ww >= 0 && ww < 256) ? s[SK18(hh + dy, ww)] : 0.f;
                acc += w9[dy * 3 + dx] * v;
            }
        }
        int win = hh * 16 + wx;
        dst[((size_t)win * 128 + dstc) * 256 + a * 16 + bcol] = acc;
    }
}

// =====================================================================================
// K3: attention, one block per (head, win). K/V staged + k-normalized ONCE, then loop
//   over eight 32-row m-tiles. Q consumed straight from global as A-fragments.
//   smem (floats): S 32x264 | Ks 16x264 | Vs 16x264 | Os 2x32x18 (union RED/RN)
//   = 18048 floats = 72192 B  -> 3 CTAs/SM.
// =====================================================================================
__global__ void __launch_bounds__(256, 3) k3_attn_mma(float* __restrict__ attn)
{
    extern __shared__ float sm[];
    float* S  = sm;                      // 8448
    float* Ks = sm + 8448;               // 4224
    float* Vs = sm + 12672;              // 4224
    float* Os = sm + 16896;              // 1152 (2 x 32 x 18)
    float* RED = Os;                     // 128 (union: used only before the loop)
    float* RN  = Os + 128;               // 16

    unsigned* Su = (unsigned*)S;
    unsigned* Ku = (unsigned*)Ks;
    unsigned* Vu = (unsigned*)Vs;

    int t    = threadIdx.x;
    int lane = t & 31, wid = t >> 5;
    int g    = lane >> 2, tig = lane & 3;
    int head = blockIdx.x;
    int win  = blockIdx.y;

    const float* qb = g_qw + ((size_t)win * 128 + head * 16) * 256;
    const float* kb = g_kw + ((size_t)win * 128 + head * 16) * 256;
    const float* vb = g_vw + ((size_t)win * 128 + head * 16) * 256;

    // ---- stage K (regs) + V (tf32 smem), once per block ----
    float kreg[16];
#pragma unroll
    for (int d = 0; d < 16; d++) kreg[d] = kb[d * 256 + t];
#pragma unroll
    for (int d = 0; d < 16; d++) Vu[d * 264 + t] = f2tf32(vb[d * 256 + t]);

    // ---- k norm over tokens per channel d, once per block ----
#pragma unroll
    for (int d = 0; d < 16; d++) {
        float ssq = kreg[d] * kreg[d];
#pragma unroll
        for (int off = 16; off > 0; off >>= 1) ssq += __shfl_xor_sync(0xFFFFFFFFu, ssq, off);
        if (lane == 0) RED[d * 8 + wid] = ssq;
    }
    __syncthreads();
    if (t < 16) {
        float s = 0.f;
#pragma unroll
        for (int j = 0; j < 8; j++) s += RED[t * 8 + j];
        RN[t] = 1.f / fmaxf(sqrtf(s), 1e-12f);
    }
    __syncthreads();
#pragma unroll
    for (int d = 0; d < 16; d++) Ku[d * 264 + t] = f2tf32(kreg[d] * RN[d]);
    __syncthreads();

    // ---- loop over 32-row m-tiles ----
    for (int mq = 0; mq < 8; mq++) {
        int m0 = mq * 32;

        // QK: warp = (mt 0..1) x (nq 0..3); tile m16 x n64, K=16. A-frags from GLOBAL q.
        {
            int mt = wid >> 2, nq = wid & 3;
            int mrow = mt * 16;
            const float* qrow = qb + m0 + mrow;
            unsigned a[2][4];
#pragma unroll
            for (int ks = 0; ks < 2; ks++) {
                int k0 = ks * 8;
                a[ks][0] = f2tf32(qrow[(k0 + tig) * 256 + g]);
                a[ks][1] = f2tf32(qrow[(k0 + tig) * 256 + 8 + g]);
                a[ks][2] = f2tf32(qrow[(k0 + tig + 4) * 256 + g]);
                a[ks][3] = f2tf32(qrow[(k0 + tig + 4) * 256 + 8 + g]);
            }
#pragma unroll
            for (int nt = 0; nt < 8; nt++) {
                int n0 = nq * 64 + nt * 8;
                float c[4] = {0.f, 0.f, 0.f, 0.f};
#pragma unroll
                for (int ks = 0; ks < 2; ks++) {
                    int k0 = ks * 8;
                    unsigned b[2] = { Ku[(k0 + tig) * 264 + n0 + g],
                                      Ku[(k0 + tig + 4) * 264 + n0 + g] };
                    mma_tf32(c, a[ks], b);
                }
                *(float2*)&S[(mrow + g) * 264 + n0 + tig * 2]     = make_float2(c[0], c[1]);
                *(float2*)&S[(mrow + 8 + g) * 264 + n0 + tig * 2] = make_float2(c[2], c[3]);
            }
        }
        __syncthreads();

        // softmax: warp = 4 rows; lane owns 8 CONTIGUOUS cols -> float4 ld/st.
#pragma unroll
        for (int r = 0; r < 4; r++) {
            int m = wid * 4 + r;
            float4 va = *(const float4*)&S[m * 264 + lane * 8];
            float4 vb4 = *(const float4*)&S[m * 264 + lane * 8 + 4];
            float mx = fmaxf(fmaxf(fmaxf(va.x, va.y), fmaxf(va.z, va.w)),
                             fmaxf(fmaxf(vb4.x, vb4.y), fmaxf(vb4.z, vb4.w)));
#pragma unroll
            for (int off = 16; off > 0; off >>= 1) mx = fmaxf(mx, __shfl_xor_sync(0xFFFFFFFFu, mx, off));
            va.x = __expf(va.x - mx); va.y = __expf(va.y - mx);
            va.z = __expf(va.z - mx); va.w = __expf(va.w - mx);
            vb4.x = __expf(vb4.x - mx); vb4.y = __expf(vb4.y - mx);
            vb4.z = __expf(vb4.z - mx); vb4.w = __expf(vb4.w - mx);
            float s = va.x + va.y + va.z + va.w + vb4.x + vb4.y + vb4.z + vb4.w;
#pragma unroll
            for (int off = 16; off > 0; off >>= 1) s += __shfl_xor_sync(0xFFFFFFFFu, s, off);
            float rinv = 1.f / s;
            va.x *= rinv; va.y *= rinv; va.z *= rinv; va.w *= rinv;
            vb4.x *= rinv; vb4.y *= rinv; vb4.z *= rinv; vb4.w *= rinv;
            float* orow = attn + ((size_t)((win * 8 + head) * 256 + m0 + m)) * 256;
            __stcs((float4*)&orow[lane * 8], va);
            __stcs((float4*)&orow[lane * 8 + 4], vb4);
            uint4 pa = make_uint4(f2tf32(va.x), f2tf32(va.y), f2tf32(va.z), f2tf32(va.w));
            uint4 pb = make_uint4(f2tf32(vb4.x), f2tf32(vb4.y), f2tf32(vb4.z), f2tf32(vb4.w));
            *(uint4*)&Su[m * 264 + lane * 8]     = pa;
            *(uint4*)&Su[m * 264 + lane * 8 + 4] = pb;
        }
        __syncthreads();

        // AV: warp = (kq 0..1, mt 0..1, dt 0..1); m16 x n8(d), K=128. Dual acc chains.
        {
            int kq = wid >> 2, mt = (wid >> 1) & 1, dt = wid & 1;
            int mrow = mt * 16, d0 = dt * 8;
            int kbase = kq * 128;
            float cA[4] = {0.f, 0.f, 0.f, 0.f};
            float cB[4] = {0.f, 0.f, 0.f, 0.f};
#pragma unroll
            for (int ks = 0; ks < 16; ks += 2) {
                int k0 = kbase + ks * 8;
                unsigned a0[4] = { Su[(mrow + g) * 264 + k0 + tig],
                                   Su[(mrow + 8 + g) * 264 + k0 + tig],
                                   Su[(mrow + g) * 264 + k0 + tig + 4],
                                   Su[(mrow + 8 + g) * 264 + k0 + tig + 4] };
                unsigned b0[2] = { Vu[(d0 + g) * 264 + k0 + tig], Vu[(d0 + g) * 264 + k0 + tig + 4] };
                mma_tf32(cA, a0, b0);
                int k1 = k0 + 8;
                unsigned a1[4] = { Su[(mrow + g) * 264 + k1 + tig],
                                   Su[(mrow + 8 + g) * 264 + k1 + tig],
                                   Su[(mrow + g) * 264 + k1 + tig + 4],
                                   Su[(mrow + 8 + g) * 264 + k1 + tig + 4] };
                unsigned b1[2] = { Vu[(d0 + g) * 264 + k1 + tig], Vu[(d0 + g) * 264 + k1 + tig + 4] };
                mma_tf32(cB, a1, b1);
            }
            cA[0] += cB[0]; cA[1] += cB[1]; cA[2] += cB[2]; cA[3] += cB[3];
            *(float2*)&Os[(kq * 32 + mrow + g) * 18 + d0 + tig * 2]     = make_float2(cA[0], cA[1]);
            *(float2*)&Os[(kq * 32 + mrow + 8 + g) * 18 + d0 + tig * 2] = make_float2(cA[2], cA[3]);
        }
        __syncthreads();

        // reduce 2 k-halves, write out_win [win][c][m] coalesced
        float* outw = g_q1;
#pragma unroll
        for (int i = 0; i < 2; i++) {
            int idx = i * 256 + t;
            int m = idx & 31, d = idx >> 5;
            float s = Os[m * 18 + d] + Os[(32 + m) * 18 + d];
            outw[((size_t)win * 128 + head * 16 + d) * 256 + m0 + m] = s;
        }
        __syncthreads();   // protect Os (and S) before next iteration's writes
    }
}

// =====================================================================================
// K4: window reverse for `out`: out_win [win][c][m] -> NCHW
// =====================================================================================
__global__ void k4_winrev(float* __restrict__ outp)
{
    __shared__ float s[16 * 272];
    int a = blockIdx.x;
    int c = blockIdx.y;
    int t = threadIdx.x;
    int g = t >> 4, bcol = t & 15;

    const float* outw = g_q1;
    for (int j = 0; j < 16; j++) {
        float v = outw[((size_t)(j * 16 + g) * 128 + c) * 256 + a * 16 + bcol];
        int col = bcol * 16 + g;
        s[j * 272 + col + (col >> 4)] = v;
    }
    __syncthreads();
    for (int j = 0; j < 16; j++) {
        int col = t;
        outp[(size_t)c * 65536 + (a * 16 + j) * 256 + t] = s[j * 272 + col + (col >> 4)];
    }
}

// =====================================================================================
extern "C" void kernel_launch(void* const* d_in, const int* in_sizes, int n_in,
                              void* d_out, int out_size)
{
    const float* lms   = (const float*)d_in[0];
    const float* pan   = (const float*)d_in[1];
    const float* gms   = (const float*)d_in[2];
    const float* gpan  = (const float*)d_in[3];
    const float* qw1   = (const float*)d_in[4];
    const float* qb1   = (const float*)d_in[5];
    const float* qw2   = (const float*)d_in[6];
    const float* qb2   = (const float*)d_in[7];
    const float* kvw1  = (const float*)d_in[8];
    const float* kvb1  = (const float*)d_in[9];
    const float* kvw2  = (const float*)d_in[10];
    const float* kvb2  = (const float*)d_in[11];

    float* attn = (float*)d_out;                   // (256, 8, 256, 256)
    float* outp = attn + 134217728;                // (1, 128, 256, 256)

    cudaFuncSetAttribute(k3_attn_mma, cudaFuncAttributeMaxDynamicSharedMemorySize, 72192);

    k1_ln_conv1<<<256, 256, 49152>>>(lms, pan, gms, gpan, qw1, qb1, kvw1, kvb1);
    k2_dwconv_scatter<<<dim3(16, 384), 256>>>(qw2, qb2, kvw2, kvb2);
    k3_attn_mma<<<dim3(8, 256), 256, 72192>>>(attn);
    k4_winrev<<<dim3(16, 128), 256>>>(outp);
}

// round 6
// speedup vs baseline: 2.0157x; 1.0070x over previous
#include <cuda_runtime.h>
#include <math.h>

// ---------------- scratch (device globals; no allocations allowed) ----------------
__device__ float g_q1[128u * 65536u];          // 32 MB : conv1 q output (NCHW), later out_win
__device__ float g_kv1[256u * 65536u];         // 64 MB : conv1 kv output (NCHW)
__device__ float g_qw[256u * 128u * 256u];     // 32 MB : q  in [win][c][m]
__device__ float g_kw[256u * 128u * 256u];     // 32 MB : k  in [win][c][m]
__device__ float g_vw[256u * 128u * 256u];     // 32 MB : v  in [win][c][m]

// =====================================================================================
// helpers
// =====================================================================================
__device__ __forceinline__ unsigned f2tf32(float f) {
    unsigned u;
    asm("cvt.rna.tf32.f32 %0, %1;" : "=r"(u) : "f"(f));
    return u;
}
__device__ __forceinline__ void mma_tf32(float c[4], const unsigned a[4], const unsigned b[2]) {
    asm volatile(
        "mma.sync.aligned.m16n8k8.row.col.f32.tf32.tf32.f32 "
        "{%0,%1,%2,%3},{%4,%5,%6,%7},{%8,%9},{%0,%1,%2,%3};"
        : "+f"(c[0]), "+f"(c[1]), "+f"(c[2]), "+f"(c[3])
        : "r"(a[0]), "r"(a[1]), "r"(a[2]), "r"(a[3]), "r"(b[0]), "r"(b[1]));
}
__device__ __forceinline__ void wg_bar(int id) {
    asm volatile("bar.sync %0, 256;" :: "r"(id) : "memory");
}

// =====================================================================================
// K1: per-pixel channel LayerNorm (C=32) + 1x1 convs -> q1[128][HW], kv1[256][HW]
// =====================================================================================
__global__ void k1_ln_conv1(const float* __restrict__ lms, const float* __restrict__ pan,
                            const float* __restrict__ gms, const float* __restrict__ gpan,
                            const float* __restrict__ qw1, const float* __restrict__ qb1,
                            const float* __restrict__ kvw1, const float* __restrict__ kvb1)
{
    extern __shared__ float sw[];
    int t = threadIdx.x;
    for (int i = t; i < 128 * 32; i += 256) sw[i] = qw1[i];
    for (int i = t; i < 256 * 32; i += 256) sw[4096 + i] = kvw1[i];
    __syncthreads();

    int p = blockIdx.x * 256 + t;

    float xp[32], xl[32];
    float sp = 0.f, sp2 = 0.f, sl = 0.f, sl2 = 0.f;
#pragma unroll
    for (int i = 0; i < 32; i++) {
        float a = pan[i * 65536 + p]; xp[i] = a; sp += a; sp2 += a * a;
        float b = lms[i * 65536 + p]; xl[i] = b; sl += b; sl2 += b * b;
    }
    float mp = sp * (1.f / 32.f), vp = sp2 * (1.f / 32.f) - mp * mp;
    float ml = sl * (1.f / 32.f), vl = sl2 * (1.f / 32.f) - ml * ml;
    float rp = rsqrtf(vp + 1e-5f);
    float rl = rsqrtf(vl + 1e-5f);
#pragma unroll
    for (int i = 0; i < 32; i++) {
        xp[i] = (xp[i] - mp) * rp * gpan[i];
        xl[i] = (xl[i] - ml) * rl * gms[i];
    }

    const float4* wq  = (const float4*)sw;
    const float4* wkv = (const float4*)(sw + 4096);
    for (int o = 0; o < 128; o += 2) {
        float acc0 = qb1[o], acc1 = qb1[o + 1];
#pragma unroll
        for (int j = 0; j < 8; j++) {
            float4 w0 = wq[o * 8 + j];
            float4 w1 = wq[(o + 1) * 8 + j];
            acc0 += w0.x * xp[4 * j] + w0.y * xp[4 * j + 1] + w0.z * xp[4 * j + 2] + w0.w * xp[4 * j + 3];
            acc1 += w1.x * xp[4 * j] + w1.y * xp[4 * j + 1] + w1.z * xp[4 * j + 2] + w1.w * xp[4 * j + 3];
        }
        g_q1[o * 65536 + p] = acc0;
        g_q1[(o + 1) * 65536 + p] = acc1;
    }
    for (int o = 0; o < 256; o += 2) {
        float acc0 = kvb1[o], acc1 = kvb1[o + 1];
#pragma unroll
        for (int j = 0; j < 8; j++) {
            float4 w0 = wkv[o * 8 + j];
            float4 w1 = wkv[(o + 1) * 8 + j];
            acc0 += w0.x * xl[4 * j] + w0.y * xl[4 * j + 1] + w0.z * xl[4 * j + 2] + w0.w * xl[4 * j + 3];
            acc1 += w1.x * xl[4 * j] + w1.y * xl[4 * j + 1] + w1.z * xl[4 * j + 2] + w1.w * xl[4 * j + 3];
        }
        g_kv1[o * 65536 + p] = acc0;
        g_kv1[(o + 1) * 65536 + p] = acc1;
    }
}

// =====================================================================================
// K2: depthwise 3x3 (SAME) + dilated-window scatter.
// =====================================================================================
#define SK18(r, c) ((r) * 272 + (c) + ((c) >> 4))

__global__ void k2_dwconv_scatter(const float* __restrict__ qw2, const float* __restrict__ qb2,
                                  const float* __restrict__ kvw2, const float* __restrict__ kvb2)
{
    __shared__ float s[18 * 272];
    int c = blockIdx.y;
    int a = blockIdx.x;
    int h0 = a * 16;
    int t = threadIdx.x;

    const float* src; float* dst; int dstc; const float* wsrc; const float* bsrc; int cw;
    if (c < 128)      { src = g_q1  + (size_t)c * 65536;         dst = g_qw; dstc = c;        wsrc = qw2;  bsrc = qb2;  cw = c; }
    else {
        int ck = c - 128;
        src = g_kv1 + (size_t)ck * 65536;
        wsrc = kvw2; bsrc = kvb2; cw = ck;
        if (ck < 128) { dst = g_kw; dstc = ck; }
        else          { dst = g_vw; dstc = ck - 128; }
    }

    float w9[9];
#pragma unroll
    for (int j = 0; j < 9; j++) w9[j] = wsrc[cw * 9 + j];
    float bias = bsrc[cw];

    for (int i = t; i < 18 * 256; i += 256) {
        int rr = i >> 8, ww = i & 255;
        int h = h0 - 1 + rr;
        float v = (h >= 0 && h < 256) ? src[h * 256 + ww] : 0.f;
        s[SK18(rr, ww)] = v;
    }
    __syncthreads();

    int g = t >> 4, bcol = t & 15;
    for (int j = 0; j < 16; j++) {
        int hh = j, wx = g;
        int wpix = bcol * 16 + wx;
        float acc = bias;
#pragma unroll
        for (int dy = 0; dy < 3; dy++) {
#pragma unroll
            for (int dx = 0; dx < 3; dx++) {
                int ww = wpix + dx - 1;
                float v = (ww >= 0 && ww < 256) ? s[SK18(hh + dy, ww)] : 0.f;
                acc += w9[dy * 3 + dx] * v;
            }
        }
        int win = hh * 16 + wx;
        dst[((size_t)win * 128 + dstc) * 256 + a * 16 + bcol] = acc;
    }
}

// =====================================================================================
// K3: attention, one block per (head, win); 512 threads = 2 warpgroups.
//   K/V staged + k-normalized once (cooperative). Then wg0 processes m-tiles 0,2,4,6
//   and wg1 tiles 1,3,5,7 as INDEPENDENT pipelines (private S/Os, named barriers).
//   smem: S0,S1 (2x 32x264) | Ks 16x264 | Vs 16x264 | Os0,Os1 (2x 2x32x18)
//   = 27648 floats = 110592 B -> 2 CTAs/SM (32 warps).
// =====================================================================================
__global__ void __launch_bounds__(512, 2) k3_attn_mma(float* __restrict__ attn)
{
    extern __shared__ float sm[];
    float* Ks = sm + 16896;              // 4224
    float* Vs = sm + 21120;              // 4224
    float* RED = sm + 25344;             // 128 (union with Os0, pre-loop only)
    float* RN  = sm + 25344 + 128;       // 16

    unsigned* Ku = (unsigned*)Ks;
    unsigned* Vu = (unsigned*)Vs;

    int t    = threadIdx.x;              // 0..511
    int wg   = t >> 8;                   // warpgroup 0/1
    int lt   = t & 255;                  // thread-in-wg
    int lane = t & 31, wid = lt >> 5;    // warp-in-wg 0..7
    int g    = lane >> 2, tig = lane & 3;
    int head = blockIdx.x;
    int win  = blockIdx.y;

    float* S  = sm + wg * 8448;                  // private 32x264
    float* Os = sm + 25344 + wg * 1152;          // private 2x32x18
    unsigned* Su = (unsigned*)S;

    const float* qb = g_qw + ((size_t)win * 128 + head * 16) * 256;
    const float* kb = g_kw + ((size_t)win * 128 + head * 16) * 256;
    const float* vb = g_vw + ((size_t)win * 128 + head * 16) * 256;

    // ---- stage: wg0 -> K (regs) + norm partials; wg1 -> V (tf32 smem) ----
    float kreg[16];
    if (wg == 0) {
#pragma unroll
        for (int d = 0; d < 16; d++) kreg[d] = kb[d * 256 + lt];
#pragma unroll
        for (int d = 0; d < 16; d++) {
            float ssq = kreg[d] * kreg[d];
#pragma unroll
            for (int off = 16; off > 0; off >>= 1) ssq += __shfl_xor_sync(0xFFFFFFFFu, ssq, off);
            if (lane == 0) RED[d * 8 + wid] = ssq;
        }
    } else {
#pragma unroll
        for (int d = 0; d < 16; d++) Vu[d * 264 + lt] = f2tf32(vb[d * 256 + lt]);
    }
    __syncthreads();
    if (t < 16) {
        float s = 0.f;
#pragma unroll
        for (int j = 0; j < 8; j++) s += RED[t * 8 + j];
        RN[t] = 1.f / fmaxf(sqrtf(s), 1e-12f);
    }
    __syncthreads();
    if (wg == 0) {
#pragma unroll
        for (int d = 0; d < 16; d++) Ku[d * 264 + lt] = f2tf32(kreg[d] * RN[d]);
    }
    __syncthreads();

    int bar = 1 + wg;   // named barrier id for this warpgroup

    // ---- each wg: 4 independent m-tiles ----
    for (int mq = wg; mq < 8; mq += 2) {
        int m0 = mq * 32;

        // QK: warp = (mt 0..1) x (nq 0..3); m16 x n64, K=16. A-frags from GLOBAL q.
        {
            int mt = wid >> 2, nq = wid & 3;
            int mrow = mt * 16;
            const float* qrow = qb + m0 + mrow;
            unsigned a[2][4];
#pragma unroll
            for (int ks = 0; ks < 2; ks++) {
                int k0 = ks * 8;
                a[ks][0] = f2tf32(qrow[(k0 + tig) * 256 + g]);
                a[ks][1] = f2tf32(qrow[(k0 + tig) * 256 + 8 + g]);
                a[ks][2] = f2tf32(qrow[(k0 + tig + 4) * 256 + g]);
                a[ks][3] = f2tf32(qrow[(k0 + tig + 4) * 256 + 8 + g]);
            }
#pragma unroll
            for (int nt = 0; nt < 8; nt++) {
                int n0 = nq * 64 + nt * 8;
                float c[4] = {0.f, 0.f, 0.f, 0.f};
#pragma unroll
                for (int ks = 0; ks < 2; ks++) {
                    int k0 = ks * 8;
                    unsigned b[2] = { Ku[(k0 + tig) * 264 + n0 + g],
                                      Ku[(k0 + tig + 4) * 264 + n0 + g] };
                    mma_tf32(c, a[ks], b);
                }
                *(float2*)&S[(mrow + g) * 264 + n0 + tig * 2]     = make_float2(c[0], c[1]);
                *(float2*)&S[(mrow + 8 + g) * 264 + n0 + tig * 2] = make_float2(c[2], c[3]);
            }
        }
        wg_bar(bar);

        // softmax: warp = 4 rows; lane owns 8 contiguous cols -> float4 ld/st.
#pragma unroll
        for (int r = 0; r < 4; r++) {
            int m = wid * 4 + r;
            float4 va  = *(const float4*)&S[m * 264 + lane * 8];
            float4 vb4 = *(const float4*)&S[m * 264 + lane * 8 + 4];
            float mx = fmaxf(fmaxf(fmaxf(va.x, va.y), fmaxf(va.z, va.w)),
                             fmaxf(fmaxf(vb4.x, vb4.y), fmaxf(vb4.z, vb4.w)));
#pragma unroll
            for (int off = 16; off > 0; off >>= 1) mx = fmaxf(mx, __shfl_xor_sync(0xFFFFFFFFu, mx, off));
            va.x = __expf(va.x - mx); va.y = __expf(va.y - mx);
            va.z = __expf(va.z - mx); va.w = __expf(va.w - mx);
            vb4.x = __expf(vb4.x - mx); vb4.y = __expf(vb4.y - mx);
            vb4.z = __expf(vb4.z - mx); vb4.w = __expf(vb4.w - mx);
            float s = va.x + va.y + va.z + va.w + vb4.x + vb4.y + vb4.z + vb4.w;
#pragma unroll
            for (int off = 16; off > 0; off >>= 1) s += __shfl_xor_sync(0xFFFFFFFFu, s, off);
            float rinv = 1.f / s;
            va.x *= rinv; va.y *= rinv; va.z *= rinv; va.w *= rinv;
            vb4.x *= rinv; vb4.y *= rinv; vb4.z *= rinv; vb4.w *= rinv;
            float* orow = attn + ((size_t)((win * 8 + head) * 256 + m0 + m)) * 256;
            __stcs((float4*)&orow[lane * 8], va);
            __stcs((float4*)&orow[lane * 8 + 4], vb4);
            uint4 pa = make_uint4(f2tf32(va.x), f2tf32(va.y), f2tf32(va.z), f2tf32(va.w));
            uint4 pb = make_uint4(f2tf32(vb4.x), f2tf32(vb4.y), f2tf32(vb4.z), f2tf32(vb4.w));
            *(uint4*)&Su[m * 264 + lane * 8]     = pa;
            *(uint4*)&Su[m * 264 + lane * 8 + 4] = pb;
        }
        wg_bar(bar);

        // AV: warp = (kq 0..1, mt 0..1, dt 0..1); m16 x n8(d), K=128. Dual acc chains.
        {
            int kq = wid >> 2, mt = (wid >> 1) & 1, dt = wid & 1;
            int mrow = mt * 16, d0 = dt * 8;
            int kbase = kq * 128;
            float cA[4] = {0.f, 0.f, 0.f, 0.f};
            float cB[4] = {0.f, 0.f, 0.f, 0.f};
#pragma unroll
            for (int ks = 0; ks < 16; ks += 2) {
                int k0 = kbase + ks * 8;
                unsigned a0[4] = { Su[(mrow + g) * 264 + k0 + tig],
                                   Su[(mrow + 8 + g) * 264 + k0 + tig],
                                   Su[(mrow + g) * 264 + k0 + tig + 4],
                                   Su[(mrow + 8 + g) * 264 + k0 + tig + 4] };
                unsigned b0[2] = { Vu[(d0 + g) * 264 + k0 + tig], Vu[(d0 + g) * 264 + k0 + tig + 4] };
                mma_tf32(cA, a0, b0);
                int k1 = k0 + 8;
                unsigned a1[4] = { Su[(mrow + g) * 264 + k1 + tig],
                                   Su[(mrow + 8 + g) * 264 + k1 + tig],
                                   Su[(mrow + g) * 264 + k1 + tig + 4],
                                   Su[(mrow + 8 + g) * 264 + k1 + tig + 4] };
                unsigned b1[2] = { Vu[(d0 + g) * 264 + k1 + tig], Vu[(d0 + g) * 264 + k1 + tig + 4] };
                mma_tf32(cB, a1, b1);
            }
            cA[0] += cB[0]; cA[1] += cB[1]; cA[2] += cB[2]; cA[3] += cB[3];
            *(float2*)&Os[(kq * 32 + mrow + g) * 18 + d0 + tig * 2]     = make_float2(cA[0], cA[1]);
            *(float2*)&Os[(kq * 32 + mrow + 8 + g) * 18 + d0 + tig * 2] = make_float2(cA[2], cA[3]);
        }
        wg_bar(bar);

        // reduce 2 k-halves, write out_win [win][c][m] coalesced
        {
            float* outw = g_q1;
            int m = lt & 31, d = lt >> 5;            // lt 0..255 -> 32 m x 8 d
            float s0 = Os[m * 18 + d]      + Os[(32 + m) * 18 + d];
            float s1 = Os[m * 18 + d + 8]  + Os[(32 + m) * 18 + d + 8];
            outw[((size_t)win * 128 + head * 16 + d) * 256 + m0 + m]       = s0;
            outw[((size_t)win * 128 + head * 16 + d + 8) * 256 + m0 + m]   = s1;
        }
        wg_bar(bar);   // protect S/Os before next iteration
    }
}

// =====================================================================================
// K4: window reverse for `out`: out_win [win][c][m] -> NCHW
// =====================================================================================
__global__ void k4_winrev(float* __restrict__ outp)
{
    __shared__ float s[16 * 272];
    int a = blockIdx.x;
    int c = blockIdx.y;
    int t = threadIdx.x;
    int g = t >> 4, bcol = t & 15;

    const float* outw = g_q1;
    for (int j = 0; j < 16; j++) {
        float v = outw[((size_t)(j * 16 + g) * 128 + c) * 256 + a * 16 + bcol];
        int col = bcol * 16 + g;
        s[j * 272 + col + (col >> 4)] = v;
    }
    __syncthreads();
    for (int j = 0; j < 16; j++) {
        int col = t;
        outp[(size_t)c * 65536 + (a * 16 + j) * 256 + t] = s[j * 272 + col + (col >> 4)];
    }
}

// =====================================================================================
extern "C" void kernel_launch(void* const* d_in, const int* in_sizes, int n_in,
                              void* d_out, int out_size)
{
    const float* lms   = (const float*)d_in[0];
    const float* pan   = (const float*)d_in[1];
    const float* gms   = (const float*)d_in[2];
    const float* gpan  = (const float*)d_in[3];
    const float* qw1   = (const float*)d_in[4];
    const float* qb1   = (const float*)d_in[5];
    const float* qw2   = (const float*)d_in[6];
    const float* qb2   = (const float*)d_in[7];
    const float* kvw1  = (const float*)d_in[8];
    const float* kvb1  = (const float*)d_in[9];
    const float* kvw2  = (const float*)d_in[10];
    const float* kvb2  = (const float*)d_in[11];

    float* attn = (float*)d_out;                   // (256, 8, 256, 256)
    float* outp = attn + 134217728;                // (1, 128, 256, 256)

    cudaFuncSetAttribute(k3_attn_mma, cudaFuncAttributeMaxDynamicSharedMemorySize, 110592);

    k1_ln_conv1<<<256, 256, 49152>>>(lms, pan, gms, gpan, qw1, qb1, kvw1, kvb1);
    k2_dwconv_scatter<<<dim3(16, 384), 256>>>(qw2, qb2, kvw2, kvb2);
    k3_attn_mma<<<dim3(8, 256), 512, 110592>>>(attn);
    k4_winrev<<<dim3(16, 128), 256>>>(outp);
}

// round 7
// speedup vs baseline: 2.6457x; 1.3126x over previous
#include <cuda_runtime.h>
#include <math.h>

// ---------------- scratch (device globals; no allocations allowed) ----------------
__device__ float g_q1[128u * 65536u];          // 32 MB : conv1 q output (NCHW), later out_win
__device__ float g_kv1[256u * 65536u];         // 64 MB : conv1 kv output (NCHW)
__device__ float g_qw[256u * 128u * 256u];     // 32 MB : q  in [win][c][m]
__device__ float g_kw[256u * 128u * 256u];     // 32 MB : k  in [win][c][m]
__device__ float g_vw[256u * 128u * 256u];     // 32 MB : v  in [win][c][m]

// =====================================================================================
// helpers
// =====================================================================================
__device__ __forceinline__ unsigned f2tf32(float f) {
    unsigned u;
    asm("cvt.rna.tf32.f32 %0, %1;" : "=r"(u) : "f"(f));
    return u;
}
__device__ __forceinline__ void mma_tf32(float c[4], const unsigned a[4], const unsigned b[2]) {
    asm volatile(
        "mma.sync.aligned.m16n8k8.row.col.f32.tf32.tf32.f32 "
        "{%0,%1,%2,%3},{%4,%5,%6,%7},{%8,%9},{%0,%1,%2,%3};"
        : "+f"(c[0]), "+f"(c[1]), "+f"(c[2]), "+f"(c[3])
        : "r"(a[0]), "r"(a[1]), "r"(a[2]), "r"(a[3]), "r"(b[0]), "r"(b[1]));
}
__device__ __forceinline__ void wg_bar(int id) {
    asm volatile("bar.sync %0, 256;" :: "r"(id) : "memory");
}

// =====================================================================================
// K1: LN (C=32 per pixel) + 1x1 convs as tf32 tensor GEMM with x hi/lo compensation.
//   C[384 x 65536] = W[384 x 32] * X[32 x 65536];  C = W*xh + W*xl (xl = x - tf32(x)).
//   grid 512 x 256 thr; block handles 128 pixels, all 384 output channels.
//   smem: Xh[64][136] + Xl[64][136]  (rows 0-31 = pan_n chans, 32-63 = lms_n chans)
// =====================================================================================
__global__ void __launch_bounds__(256, 2) k1_ln_conv1(
    const float* __restrict__ lms, const float* __restrict__ pan,
    const float* __restrict__ gms, const float* __restrict__ gpan,
    const float* __restrict__ qw1, const float* __restrict__ qb1,
    const float* __restrict__ kvw1, const float* __restrict__ kvb1)
{
    extern __shared__ float sw[];
    unsigned* Xh = (unsigned*)sw;            // 64 x 136
    unsigned* Xl = (unsigned*)(sw + 8704);   // 64 x 136

    int t = threadIdx.x;
    int lane = t & 31, w = t >> 5;
    int g = lane >> 2, tig = lane & 3;
    int p0 = blockIdx.x * 128;

    // ---- hoist W a-frags from global (L2-resident after first blocks) ----
    // warp w covers mtile j: rows R = j*128 + w*16  (j=0 -> q weights, j>=1 -> kv)
    unsigned a[3][4][4];
    float bias0[3], bias1[3];
#pragma unroll
    for (int j = 0; j < 3; j++) {
        int R = j * 128 + w * 16;
        const float* Wsrc = (j == 0) ? qw1 : kvw1;
        int r0 = (j == 0) ? R : (R - 128);
#pragma unroll
        for (int ks = 0; ks < 4; ks++) {
            int k0 = ks * 8;
            a[j][ks][0] = f2tf32(Wsrc[(r0 + g) * 32 + k0 + tig]);
            a[j][ks][1] = f2tf32(Wsrc[(r0 + 8 + g) * 32 + k0 + tig]);
            a[j][ks][2] = f2tf32(Wsrc[(r0 + g) * 32 + k0 + tig + 4]);
            a[j][ks][3] = f2tf32(Wsrc[(r0 + 8 + g) * 32 + k0 + tig + 4]);
        }
        const float* Bsrc = (j == 0) ? qb1 : kvb1;
        bias0[j] = Bsrc[r0 + g];
        bias1[j] = Bsrc[r0 + 8 + g];
    }

    // ---- LN: threads 0-127 do pan pixel, 128-255 do lms pixel ----
    {
        int which = t >> 7;            // 0 = pan, 1 = lms
        int px = t & 127;
        const float* src = which ? lms : pan;
        const float* gg  = which ? gms : gpan;
        float x[32];
        float s = 0.f, s2 = 0.f;
#pragma unroll
        for (int i = 0; i < 32; i++) {
            float v = src[i * 65536 + p0 + px];
            x[i] = v; s += v; s2 += v * v;
        }
        float m = s * (1.f / 32.f);
        float var = s2 * (1.f / 32.f) - m * m;
        float r = rsqrtf(var + 1e-5f);
#pragma unroll
        for (int i = 0; i < 32; i++) {
            float xn = (x[i] - m) * r * gg[i];
            unsigned xh = f2tf32(xn);
            unsigned xl = f2tf32(xn - __uint_as_float(xh));
            int row = which * 32 + i;
            Xh[row * 136 + px] = xh;
            Xl[row * 136 + px] = xl;
        }
    }
    __syncthreads();

    // ---- GEMM: per warp, 3 mtiles x 16 ntiles; K=32 (4 ks), 2 mma per ks (hi+lo) ----
    for (int nt = 0; nt < 16; nt++) {
        int n0 = nt * 8;
        // b-frags shared across the 3 mtiles of this warp (per x-type: j0 pan, j>=1 lms)
#pragma unroll
        for (int j = 0; j < 3; j++) {
            int xrow = (j > 0) ? 32 : 0;
            float c[4] = {bias0[j], bias0[j], bias1[j], bias1[j]};
#pragma unroll
            for (int ks = 0; ks < 4; ks++) {
                int k0 = ks * 8;
                unsigned bh[2] = { Xh[(xrow + k0 + tig) * 136 + n0 + g],
                                   Xh[(xrow + k0 + tig + 4) * 136 + n0 + g] };
                mma_tf32(c, a[j][ks], bh);
                unsigned bl[2] = { Xl[(xrow + k0 + tig) * 136 + n0 + g],
                                   Xl[(xrow + k0 + tig + 4) * 136 + n0 + g] };
                mma_tf32(c, a[j][ks], bl);
            }
            int R = j * 128 + w * 16;
            int px = p0 + n0 + tig * 2;
            int row0 = R + g, row1 = R + 8 + g;
            float* d0 = (row0 < 128) ? (g_q1 + (size_t)row0 * 65536)
                                     : (g_kv1 + (size_t)(row0 - 128) * 65536);
            float* d1 = (row1 < 128) ? (g_q1 + (size_t)row1 * 65536)
                                     : (g_kv1 + (size_t)(row1 - 128) * 65536);
            *(float2*)&d0[px] = make_float2(c[0], c[1]);
            *(float2*)&d1[px] = make_float2(c[2], c[3]);
        }
    }
}

// =====================================================================================
// K2: depthwise 3x3 (SAME) + dilated-window scatter. (unchanged)
// =====================================================================================
#define SK18(r, c) ((r) * 272 + (c) + ((c) >> 4))

__global__ void k2_dwconv_scatter(const float* __restrict__ qw2, const float* __restrict__ qb2,
                                  const float* __restrict__ kvw2, const float* __restrict__ kvb2)
{
    __shared__ float s[18 * 272];
    int c = blockIdx.y;
    int a = blockIdx.x;
    int h0 = a * 16;
    int t = threadIdx.x;

    const float* src; float* dst; int dstc; const float* wsrc; const float* bsrc; int cw;
    if (c < 128)      { src = g_q1  + (size_t)c * 65536;         dst = g_qw; dstc = c;        wsrc = qw2;  bsrc = qb2;  cw = c; }
    else {
        int ck = c - 128;
        src = g_kv1 + (size_t)ck * 65536;
        wsrc = kvw2; bsrc = kvb2; cw = ck;
        if (ck < 128) { dst = g_kw; dstc = ck; }
        else          { dst = g_vw; dstc = ck - 128; }
    }

    float w9[9];
#pragma unroll
    for (int j = 0; j < 9; j++) w9[j] = wsrc[cw * 9 + j];
    float bias = bsrc[cw];

    for (int i = t; i < 18 * 256; i += 256) {
        int rr = i >> 8, ww = i & 255;
        int h = h0 - 1 + rr;
        float v = (h >= 0 && h < 256) ? src[h * 256 + ww] : 0.f;
        s[SK18(rr, ww)] = v;
    }
    __syncthreads();

    int g = t >> 4, bcol = t & 15;
    for (int j = 0; j < 16; j++) {
        int hh = j, wx = g;
        int wpix = bcol * 16 + wx;
        float acc = bias;
#pragma unroll
        for (int dy = 0; dy < 3; dy++) {
#pragma unroll
            for (int dx = 0; dx < 3; dx++) {
                int ww = wpix + dx - 1;
                float v = (ww >= 0 && ww < 256) ? s[SK18(hh + dy, ww)] : 0.f;
                acc += w9[dy * 3 + dx] * v;
            }
        }
        int win = hh * 16 + wx;
        dst[((size_t)win * 128 + dstc) * 256 + a * 16 + bcol] = acc;
    }
}

// =====================================================================================
// K3: attention, one block per (head, win); 512 threads = 2 warpgroup streams.
//   Conflict-free pitches: S,V = 260 (AV scalar frags hit all 32 banks), K = 264
//   (QK b-frags conflict-free). Softmax lane owns cols [lane*4] and [128+lane*4]
//   -> conflict-free LDS.128/STS.128 and fully coalesced 512B attn stores.
//   smem: S0,S1 32x260 | Ks 16x264 | Vs 16x260 | Os0,Os1 2x32x18 = 109312 B -> 2 CTA/SM.
// =====================================================================================
__global__ void __launch_bounds__(512, 2) k3_attn_mma(float* __restrict__ attn)
{
    extern __shared__ float sm[];
    float* Ks  = sm + 16640;             // 16 x 264
    float* Vs  = sm + 20864;             // 16 x 260
    float* RED = sm + 25024;             // union with Os0 (pre-loop only)
    float* RN  = sm + 25024 + 128;

    unsigned* Ku = (unsigned*)Ks;
    unsigned* Vu = (unsigned*)Vs;

    int t    = threadIdx.x;              // 0..511
    int wg   = t >> 8;
    int lt   = t & 255;
    int lane = t & 31, wid = lt >> 5;
    int g    = lane >> 2, tig = lane & 3;
    int head = blockIdx.x;
    int win  = blockIdx.y;

    float* S  = sm + wg * 8320;                  // private 32 x 260
    float* Os = sm + 25024 + wg * 1152;          // private 2 x 32 x 18
    unsigned* Su = (unsigned*)S;

    const float* qb = g_qw + ((size_t)win * 128 + head * 16) * 256;
    const float* kb = g_kw + ((size_t)win * 128 + head * 16) * 256;
    const float* vb = g_vw + ((size_t)win * 128 + head * 16) * 256;

    // ---- stage: wg0 -> K + norm partials; wg1 -> V ----
    float kreg[16];
    if (wg == 0) {
#pragma unroll
        for (int d = 0; d < 16; d++) kreg[d] = kb[d * 256 + lt];
#pragma unroll
        for (int d = 0; d < 16; d++) {
            float ssq = kreg[d] * kreg[d];
#pragma unroll
            for (int off = 16; off > 0; off >>= 1) ssq += __shfl_xor_sync(0xFFFFFFFFu, ssq, off);
            if (lane == 0) RED[d * 8 + wid] = ssq;
        }
    } else {
#pragma unroll
        for (int d = 0; d < 16; d++) Vu[d * 260 + lt] = f2tf32(vb[d * 256 + lt]);
    }
    __syncthreads();
    if (t < 16) {
        float s = 0.f;
#pragma unroll
        for (int j = 0; j < 8; j++) s += RED[t * 8 + j];
        RN[t] = 1.f / fmaxf(sqrtf(s), 1e-12f);
    }
    __syncthreads();
    if (wg == 0) {
#pragma unroll
        for (int d = 0; d < 16; d++) Ku[d * 264 + lt] = f2tf32(kreg[d] * RN[d]);
    }
    __syncthreads();

    int bar = 1 + wg;

    for (int mq = wg; mq < 8; mq += 2) {
        int m0 = mq * 32;

        // QK: warp = (mt 0..1) x (nq 0..3); m16 x n64, K=16. A-frags from GLOBAL q.
        {
            int mt = wid >> 2, nq = wid & 3;
            int mrow = mt * 16;
            const float* qrow = qb + m0 + mrow;
            unsigned a[2][4];
#pragma unroll
            for (int ks = 0; ks < 2; ks++) {
                int k0 = ks * 8;
                a[ks][0] = f2tf32(qrow[(k0 + tig) * 256 + g]);
                a[ks][1] = f2tf32(qrow[(k0 + tig) * 256 + 8 + g]);
                a[ks][2] = f2tf32(qrow[(k0 + tig + 4) * 256 + g]);
                a[ks][3] = f2tf32(qrow[(k0 + tig + 4) * 256 + 8 + g]);
            }
#pragma unroll
            for (int nt = 0; nt < 8; nt++) {
                int n0 = nq * 64 + nt * 8;
                float c[4] = {0.f, 0.f, 0.f, 0.f};
#pragma unroll
                for (int ks = 0; ks < 2; ks++) {
                    int k0 = ks * 8;
                    unsigned b[2] = { Ku[(k0 + tig) * 264 + n0 + g],
                                      Ku[(k0 + tig + 4) * 264 + n0 + g] };
                    mma_tf32(c, a[ks], b);
                }
                *(float2*)&S[(mrow + g) * 260 + n0 + tig * 2]     = make_float2(c[0], c[1]);
                *(float2*)&S[(mrow + 8 + g) * 260 + n0 + tig * 2] = make_float2(c[2], c[3]);
            }
        }
        wg_bar(bar);

        // softmax: warp = 4 rows; lane owns cols [lane*4] and [128+lane*4].
#pragma unroll
        for (int r = 0; r < 4; r++) {
            int m = wid * 4 + r;
            float4 va  = *(const float4*)&S[m * 260 + lane * 4];
            float4 vb4 = *(const float4*)&S[m * 260 + 128 + lane * 4];
            float mx = fmaxf(fmaxf(fmaxf(va.x, va.y), fmaxf(va.z, va.w)),
                             fmaxf(fmaxf(vb4.x, vb4.y), fmaxf(vb4.z, vb4.w)));
#pragma unroll
            for (int off = 16; off > 0; off >>= 1) mx = fmaxf(mx, __shfl_xor_sync(0xFFFFFFFFu, mx, off));
            va.x = __expf(va.x - mx); va.y = __expf(va.y - mx);
            va.z = __expf(va.z - mx); va.w = __expf(va.w - mx);
            vb4.x = __expf(vb4.x - mx); vb4.y = __expf(vb4.y - mx);
            vb4.z = __expf(vb4.z - mx); vb4.w = __expf(vb4.w - mx);
            float s = va.x + va.y + va.z + va.w + vb4.x + vb4.y + vb4.z + vb4.w;
#pragma unroll
            for (int off = 16; off > 0; off >>= 1) s += __shfl_xor_sync(0xFFFFFFFFu, s, off);
            float rinv = 1.f / s;
            va.x *= rinv; va.y *= rinv; va.z *= rinv; va.w *= rinv;
            vb4.x *= rinv; vb4.y *= rinv; vb4.z *= rinv; vb4.w *= rinv;
            float* orow = attn + ((size_t)((win * 8 + head) * 256 + m0 + m)) * 256;
            __stcs((float4*)&orow[lane * 4], va);
            __stcs((float4*)&orow[128 + lane * 4], vb4);
            uint4 pa = make_uint4(f2tf32(va.x), f2tf32(va.y), f2tf32(va.z), f2tf32(va.w));
            uint4 pb = make_uint4(f2tf32(vb4.x), f2tf32(vb4.y), f2tf32(vb4.z), f2tf32(vb4.w));
            *(uint4*)&Su[m * 260 + lane * 4]       = pa;
            *(uint4*)&Su[m * 260 + 128 + lane * 4] = pb;
        }
        wg_bar(bar);

        // AV: warp = (kq, mt, dt); m16 x n8(d), K=128. Dual acc chains.
        {
            int kq = wid >> 2, mt = (wid >> 1) & 1, dt = wid & 1;
            int mrow = mt * 16, d0 = dt * 8;
            int kbase = kq * 128;
            float cA[4] = {0.f, 0.f, 0.f, 0.f};
            float cB[4] = {0.f, 0.f, 0.f, 0.f};
#pragma unroll
            for (int ks = 0; ks < 16; ks += 2) {
                int k0 = kbase + ks * 8;
                unsigned a0[4] = { Su[(mrow + g) * 260 + k0 + tig],
                                   Su[(mrow + 8 + g) * 260 + k0 + tig],
                                   Su[(mrow + g) * 260 + k0 + tig + 4],
                                   Su[(mrow + 8 + g) * 260 + k0 + tig + 4] };
                unsigned b0[2] = { Vu[(d0 + g) * 260 + k0 + tig], Vu[(d0 + g) * 260 + k0 + tig + 4] };
                mma_tf32(cA, a0, b0);
                int k1 = k0 + 8;
                unsigned a1[4] = { Su[(mrow + g) * 260 + k1 + tig],
                                   Su[(mrow + 8 + g) * 260 + k1 + tig],
                                   Su[(mrow + g) * 260 + k1 + tig + 4],
                                   Su[(mrow + 8 + g) * 260 + k1 + tig + 4] };
                unsigned b1[2] = { Vu[(d0 + g) * 260 + k1 + tig], Vu[(d0 + g) * 260 + k1 + tig + 4] };
                mma_tf32(cB, a1, b1);
            }
            cA[0] += cB[0]; cA[1] += cB[1]; cA[2] += cB[2]; cA[3] += cB[3];
            *(float2*)&Os[(kq * 32 + mrow + g) * 18 + d0 + tig * 2]     = make_float2(cA[0], cA[1]);
            *(float2*)&Os[(kq * 32 + mrow + 8 + g) * 18 + d0 + tig * 2] = make_float2(cA[2], cA[3]);
        }
        wg_bar(bar);

        // reduce 2 k-halves, write out_win [win][c][m] coalesced
        {
            float* outw = g_q1;
            int m = lt & 31, d = lt >> 5;
            float s0 = Os[m * 18 + d]      + Os[(32 + m) * 18 + d];
            float s1 = Os[m * 18 + d + 8]  + Os[(32 + m) * 18 + d + 8];
            outw[((size_t)win * 128 + head * 16 + d) * 256 + m0 + m]     = s0;
            outw[((size_t)win * 128 + head * 16 + d + 8) * 256 + m0 + m] = s1;
        }
        wg_bar(bar);
    }
}

// =====================================================================================
// K4: window reverse for `out`: out_win [win][c][m] -> NCHW (unchanged)
// =====================================================================================
__global__ void k4_winrev(float* __restrict__ outp)
{
    __shared__ float s[16 * 272];
    int a = blockIdx.x;
    int c = blockIdx.y;
    int t = threadIdx.x;
    int g = t >> 4, bcol = t & 15;

    const float* outw = g_q1;
    for (int j = 0; j < 16; j++) {
        float v = outw[((size_t)(j * 16 + g) * 128 + c) * 256 + a * 16 + bcol];
        int col = bcol * 16 + g;
        s[j * 272 + col + (col >> 4)] = v;
    }
    __syncthreads();
    for (int j = 0; j < 16; j++) {
        int col = t;
        outp[(size_t)c * 65536 + (a * 16 + j) * 256 + t] = s[j * 272 + col + (col >> 4)];
    }
}

// =====================================================================================
extern "C" void kernel_launch(void* const* d_in, const int* in_sizes, int n_in,
                              void* d_out, int out_size)
{
    const float* lms   = (const float*)d_in[0];
    const float* pan   = (const float*)d_in[1];
    const float* gms   = (const float*)d_in[2];
    const float* gpan  = (const float*)d_in[3];
    const float* qw1   = (const float*)d_in[4];
    const float* qb1   = (const float*)d_in[5];
    const float* qw2   = (const float*)d_in[6];
    const float* qb2   = (const float*)d_in[7];
    const float* kvw1  = (const float*)d_in[8];
    const float* kvb1  = (const float*)d_in[9];
    const float* kvw2  = (const float*)d_in[10];
    const float* kvb2  = (const float*)d_in[11];

    float* attn = (float*)d_out;                   // (256, 8, 256, 256)
    float* outp = attn + 134217728;                // (1, 128, 256, 256)

    cudaFuncSetAttribute(k1_ln_conv1, cudaFuncAttributeMaxDynamicSharedMemorySize, 69632);
    cudaFuncSetAttribute(k3_attn_mma, cudaFuncAttributeMaxDynamicSharedMemorySize, 109312);

    k1_ln_conv1<<<512, 256, 69632>>>(lms, pan, gms, gpan, qw1, qb1, kvw1, kvb1);
    k2_dwconv_scatter<<<dim3(16, 384), 256>>>(qw2, qb2, kvw2, kvb2);
    k3_attn_mma<<<dim3(8, 256), 512, 109312>>>(attn);
    k4_winrev<<<dim3(16, 128), 256>>>(outp);
}

// round 8
// speedup vs baseline: 2.7415x; 1.0362x over previous
#include <cuda_runtime.h>
#include <math.h>

// ---------------- scratch (device globals; no allocations allowed) ----------------
__device__ float g_q1[128u * 65536u];          // 32 MB : conv1 q output (NCHW), later out_win
__device__ float g_kv1[256u * 65536u];         // 64 MB : conv1 kv output (NCHW)
__device__ float g_qw[256u * 128u * 256u];     // 32 MB : q  in [win][c][m]
__device__ float g_kw[256u * 128u * 256u];     // 32 MB : k  in [win][c][m]
__device__ float g_vw[256u * 128u * 256u];     // 32 MB : v  in [win][c][m]

// =====================================================================================
// helpers
// =====================================================================================
__device__ __forceinline__ unsigned f2tf32(float f) {
    unsigned u;
    asm("cvt.rna.tf32.f32 %0, %1;" : "=r"(u) : "f"(f));
    return u;
}
__device__ __forceinline__ void mma_tf32(float c[4], const unsigned a[4], const unsigned b[2]) {
    asm volatile(
        "mma.sync.aligned.m16n8k8.row.col.f32.tf32.tf32.f32 "
        "{%0,%1,%2,%3},{%4,%5,%6,%7},{%8,%9},{%0,%1,%2,%3};"
        : "+f"(c[0]), "+f"(c[1]), "+f"(c[2]), "+f"(c[3])
        : "r"(a[0]), "r"(a[1]), "r"(a[2]), "r"(a[3]), "r"(b[0]), "r"(b[1]));
}

// =====================================================================================
// K1: LN + 1x1 convs as tf32 tensor GEMM with x hi/lo compensation. (unchanged)
// =====================================================================================
__global__ void __launch_bounds__(256, 2) k1_ln_conv1(
    const float* __restrict__ lms, const float* __restrict__ pan,
    const float* __restrict__ gms, const float* __restrict__ gpan,
    const float* __restrict__ qw1, const float* __restrict__ qb1,
    const float* __restrict__ kvw1, const float* __restrict__ kvb1)
{
    extern __shared__ float sw[];
    unsigned* Xh = (unsigned*)sw;            // 64 x 136
    unsigned* Xl = (unsigned*)(sw + 8704);   // 64 x 136

    int t = threadIdx.x;
    int lane = t & 31, w = t >> 5;
    int g = lane >> 2, tig = lane & 3;
    int p0 = blockIdx.x * 128;

    unsigned a[3][4][4];
    float bias0[3], bias1[3];
#pragma unroll
    for (int j = 0; j < 3; j++) {
        int R = j * 128 + w * 16;
        const float* Wsrc = (j == 0) ? qw1 : kvw1;
        int r0 = (j == 0) ? R : (R - 128);
#pragma unroll
        for (int ks = 0; ks < 4; ks++) {
            int k0 = ks * 8;
            a[j][ks][0] = f2tf32(Wsrc[(r0 + g) * 32 + k0 + tig]);
            a[j][ks][1] = f2tf32(Wsrc[(r0 + 8 + g) * 32 + k0 + tig]);
            a[j][ks][2] = f2tf32(Wsrc[(r0 + g) * 32 + k0 + tig + 4]);
            a[j][ks][3] = f2tf32(Wsrc[(r0 + 8 + g) * 32 + k0 + tig + 4]);
        }
        const float* Bsrc = (j == 0) ? qb1 : kvb1;
        bias0[j] = Bsrc[r0 + g];
        bias1[j] = Bsrc[r0 + 8 + g];
    }

    {
        int which = t >> 7;
        int px = t & 127;
        const float* src = which ? lms : pan;
        const float* gg  = which ? gms : gpan;
        float x[32];
        float s = 0.f, s2 = 0.f;
#pragma unroll
        for (int i = 0; i < 32; i++) {
            float v = src[i * 65536 + p0 + px];
            x[i] = v; s += v; s2 += v * v;
        }
        float m = s * (1.f / 32.f);
        float var = s2 * (1.f / 32.f) - m * m;
        float r = rsqrtf(var + 1e-5f);
#pragma unroll
        for (int i = 0; i < 32; i++) {
            float xn = (x[i] - m) * r * gg[i];
            unsigned xh = f2tf32(xn);
            unsigned xl = f2tf32(xn - __uint_as_float(xh));
            int row = which * 32 + i;
            Xh[row * 136 + px] = xh;
            Xl[row * 136 + px] = xl;
        }
    }
    __syncthreads();

    for (int nt = 0; nt < 16; nt++) {
        int n0 = nt * 8;
#pragma unroll
        for (int j = 0; j < 3; j++) {
            int xrow = (j > 0) ? 32 : 0;
            float c[4] = {bias0[j], bias0[j], bias1[j], bias1[j]};
#pragma unroll
            for (int ks = 0; ks < 4; ks++) {
                int k0 = ks * 8;
                unsigned bh[2] = { Xh[(xrow + k0 + tig) * 136 + n0 + g],
                                   Xh[(xrow + k0 + tig + 4) * 136 + n0 + g] };
                mma_tf32(c, a[j][ks], bh);
                unsigned bl[2] = { Xl[(xrow + k0 + tig) * 136 + n0 + g],
                                   Xl[(xrow + k0 + tig + 4) * 136 + n0 + g] };
                mma_tf32(c, a[j][ks], bl);
            }
            int R = j * 128 + w * 16;
            int px = p0 + n0 + tig * 2;
            int row0 = R + g, row1 = R + 8 + g;
            float* d0 = (row0 < 128) ? (g_q1 + (size_t)row0 * 65536)
                                     : (g_kv1 + (size_t)(row0 - 128) * 65536);
            float* d1 = (row1 < 128) ? (g_q1 + (size_t)row1 * 65536)
                                     : (g_kv1 + (size_t)(row1 - 128) * 65536);
            *(float2*)&d0[px] = make_float2(c[0], c[1]);
            *(float2*)&d1[px] = make_float2(c[2], c[3]);
        }
    }
}

// =====================================================================================
// K2: depthwise 3x3 (SAME) + dilated-window scatter. (unchanged)
// =====================================================================================
#define SK18(r, c) ((r) * 272 + (c) + ((c) >> 4))

__global__ void k2_dwconv_scatter(const float* __restrict__ qw2, const float* __restrict__ qb2,
                                  const float* __restrict__ kvw2, const float* __restrict__ kvb2)
{
    __shared__ float s[18 * 272];
    int c = blockIdx.y;
    int a = blockIdx.x;
    int h0 = a * 16;
    int t = threadIdx.x;

    const float* src; float* dst; int dstc; const float* wsrc; const float* bsrc; int cw;
    if (c < 128)      { src = g_q1  + (size_t)c * 65536;         dst = g_qw; dstc = c;        wsrc = qw2;  bsrc = qb2;  cw = c; }
    else {
        int ck = c - 128;
        src = g_kv1 + (size_t)ck * 65536;
        wsrc = kvw2; bsrc = kvb2; cw = ck;
        if (ck < 128) { dst = g_kw; dstc = ck; }
        else          { dst = g_vw; dstc = ck - 128; }
    }

    float w9[9];
#pragma unroll
    for (int j = 0; j < 9; j++) w9[j] = wsrc[cw * 9 + j];
    float bias = bsrc[cw];

    for (int i = t; i < 18 * 256; i += 256) {
        int rr = i >> 8, ww = i & 255;
        int h = h0 - 1 + rr;
        float v = (h >= 0 && h < 256) ? src[h * 256 + ww] : 0.f;
        s[SK18(rr, ww)] = v;
    }
    __syncthreads();

    int g = t >> 4, bcol = t & 15;
    for (int j = 0; j < 16; j++) {
        int hh = j, wx = g;
        int wpix = bcol * 16 + wx;
        float acc = bias;
#pragma unroll
        for (int dy = 0; dy < 3; dy++) {
#pragma unroll
            for (int dx = 0; dx < 3; dx++) {
                int ww = wpix + dx - 1;
                float v = (ww >= 0 && ww < 256) ? s[SK18(hh + dy, ww)] : 0.f;
                acc += w9[dy * 3 + dx] * v;
            }
        }
        int win = hh * 16 + wx;
        dst[((size_t)win * 128 + dstc) * 256 + a * 16 + bcol] = acc;
    }
}

// =====================================================================================
// K3: attention, one block per (head, win), 256 threads, register-resident probs.
//   QK accumulators stay in regs; softmax via tig-quad shfl + 128-float cross-warp
//   partials; AV consumes P via in-warp C->A fragment shuffle. NO logits/probs smem.
//   smem: Ks 16x264 | Vs 16x260 | Os 4x32x18 | REDM/REDS 128+128 | RN 16 = 43840 B
//   -> 4 CTAs/SM (32 warps).
// =====================================================================================
__global__ void __launch_bounds__(256, 4) k3_attn_mma(float* __restrict__ attn)
{
    extern __shared__ float sm[];
    float* Ks   = sm;                    // 4224
    float* Vs   = sm + 4224;             // 4160
    float* Os   = sm + 8384;             // 2304 (4 nq x 32 x 18)
    float* REDM = sm + 10688;            // 128
    float* REDS = sm + 10816;            // 128
    float* RN   = sm + 10944;            // 16

    unsigned* Ku = (unsigned*)Ks;
    unsigned* Vu = (unsigned*)Vs;

    int t    = threadIdx.x;
    int lane = t & 31, wid = t >> 5;
    int g    = lane >> 2, tig = lane & 3;
    int head = blockIdx.x;
    int win  = blockIdx.y;

    const float* qb = g_qw + ((size_t)win * 128 + head * 16) * 256;
    const float* kb = g_kw + ((size_t)win * 128 + head * 16) * 256;
    const float* vb = g_vw + ((size_t)win * 128 + head * 16) * 256;

    // ---- stage K (regs) + V (tf32 smem) ----
    float kreg[16];
#pragma unroll
    for (int d = 0; d < 16; d++) kreg[d] = kb[d * 256 + t];
#pragma unroll
    for (int d = 0; d < 16; d++) Vu[d * 260 + t] = f2tf32(vb[d * 256 + t]);

    // ---- k norm over tokens per channel d ----
#pragma unroll
    for (int d = 0; d < 16; d++) {
        float ssq = kreg[d] * kreg[d];
#pragma unroll
        for (int off = 16; off > 0; off >>= 1) ssq += __shfl_xor_sync(0xFFFFFFFFu, ssq, off);
        if (lane == 0) REDM[d * 8 + wid] = ssq;
    }
    __syncthreads();
    if (t < 16) {
        float s = 0.f;
#pragma unroll
        for (int j = 0; j < 8; j++) s += REDM[t * 8 + j];
        RN[t] = 1.f / fmaxf(sqrtf(s), 1e-12f);
    }
    __syncthreads();
#pragma unroll
    for (int d = 0; d < 16; d++) Ku[d * 264 + t] = f2tf32(kreg[d] * RN[d]);
    __syncthreads();

    int mt = wid >> 2, nq = wid & 3;     // warp role, fixed across tiles
    int mrow = mt * 16;
    int srcA = (lane & 0x1C) + (tig >> 1);  // C->A shuffle source (col tig)
    int par  = tig & 1;

    for (int mq = 0; mq < 8; mq++) {
        int m0 = mq * 32;

        // ---- QK: m16 x n64 per warp, K=16; A-frags from global q ----
        float c[8][4];
        {
            const float* qrow = qb + m0 + mrow;
            unsigned a[2][4];
#pragma unroll
            for (int ks = 0; ks < 2; ks++) {
                int k0 = ks * 8;
                a[ks][0] = f2tf32(qrow[(k0 + tig) * 256 + g]);
                a[ks][1] = f2tf32(qrow[(k0 + tig) * 256 + 8 + g]);
                a[ks][2] = f2tf32(qrow[(k0 + tig + 4) * 256 + g]);
                a[ks][3] = f2tf32(qrow[(k0 + tig + 4) * 256 + 8 + g]);
            }
#pragma unroll
            for (int nt = 0; nt < 8; nt++) {
                int n0 = nq * 64 + nt * 8;
                c[nt][0] = 0.f; c[nt][1] = 0.f; c[nt][2] = 0.f; c[nt][3] = 0.f;
#pragma unroll
                for (int ks = 0; ks < 2; ks++) {
                    int k0 = ks * 8;
                    unsigned b[2] = { Ku[(k0 + tig) * 264 + n0 + g],
                                      Ku[(k0 + tig + 4) * 264 + n0 + g] };
                    mma_tf32(c[nt], a[ks], b);
                }
            }
        }

        // ---- softmax, fused. rows rA = mrow+g, rB = mrow+8+g ----
        int rA = mrow + g, rB = mrow + 8 + g;
        {
            float mA = -3.0e38f, mB = -3.0e38f;
#pragma unroll
            for (int nt = 0; nt < 8; nt++) {
                mA = fmaxf(mA, fmaxf(c[nt][0], c[nt][1]));
                mB = fmaxf(mB, fmaxf(c[nt][2], c[nt][3]));
            }
            mA = fmaxf(mA, __shfl_xor_sync(0xFFFFFFFFu, mA, 1));
            mA = fmaxf(mA, __shfl_xor_sync(0xFFFFFFFFu, mA, 2));
            mB = fmaxf(mB, __shfl_xor_sync(0xFFFFFFFFu, mB, 1));
            mB = fmaxf(mB, __shfl_xor_sync(0xFFFFFFFFu, mB, 2));
            if (tig == 0) { REDM[rA * 4 + nq] = mA; REDM[rB * 4 + nq] = mB; }
        }
        __syncthreads();
        {
            float mA = fmaxf(fmaxf(REDM[rA * 4], REDM[rA * 4 + 1]),
                             fmaxf(REDM[rA * 4 + 2], REDM[rA * 4 + 3]));
            float mB = fmaxf(fmaxf(REDM[rB * 4], REDM[rB * 4 + 1]),
                             fmaxf(REDM[rB * 4 + 2], REDM[rB * 4 + 3]));
            float sA = 0.f, sB = 0.f;
#pragma unroll
            for (int nt = 0; nt < 8; nt++) {
                c[nt][0] = __expf(c[nt][0] - mA); c[nt][1] = __expf(c[nt][1] - mA);
                c[nt][2] = __expf(c[nt][2] - mB); c[nt][3] = __expf(c[nt][3] - mB);
                sA += c[nt][0] + c[nt][1];
                sB += c[nt][2] + c[nt][3];
            }
            sA += __shfl_xor_sync(0xFFFFFFFFu, sA, 1);
            sA += __shfl_xor_sync(0xFFFFFFFFu, sA, 2);
            sB += __shfl_xor_sync(0xFFFFFFFFu, sB, 1);
            sB += __shfl_xor_sync(0xFFFFFFFFu, sB, 2);
            if (tig == 0) { REDS[rA * 4 + nq] = sA; REDS[rB * 4 + nq] = sB; }
        }
        __syncthreads();
        {
            float rinvA = 1.f / (REDS[rA * 4] + REDS[rA * 4 + 1] + REDS[rA * 4 + 2] + REDS[rA * 4 + 3]);
            float rinvB = 1.f / (REDS[rB * 4] + REDS[rB * 4 + 1] + REDS[rB * 4 + 2] + REDS[rB * 4 + 3]);
            float* oA = attn + ((size_t)((win * 8 + head) * 256 + m0 + rA)) * 256;
            float* oB = attn + ((size_t)((win * 8 + head) * 256 + m0 + rB)) * 256;
#pragma unroll
            for (int nt = 0; nt < 8; nt++) {
                int n0 = nq * 64 + nt * 8 + tig * 2;
                c[nt][0] *= rinvA; c[nt][1] *= rinvA;
                c[nt][2] *= rinvB; c[nt][3] *= rinvB;
                __stcs((float2*)&oA[n0], make_float2(c[nt][0], c[nt][1]));
                __stcs((float2*)&oB[n0], make_float2(c[nt][2], c[nt][3]));
            }
        }

        // ---- AV: P (regs, via C->A shuffle) x V (smem). O partial m16 x d16 ----
        {
            float o0[4] = {0.f, 0.f, 0.f, 0.f};   // d 0..7
            float o1[4] = {0.f, 0.f, 0.f, 0.f};   // d 8..15
#pragma unroll
            for (int nt = 0; nt < 8; nt++) {
                int k0 = nq * 64 + nt * 8;        // token base of this k8 block
                // C->A fragment conversion
                float x0 = __shfl_sync(0xFFFFFFFFu, c[nt][0], srcA);
                float x1 = __shfl_sync(0xFFFFFFFFu, c[nt][1], srcA);
                float x2 = __shfl_sync(0xFFFFFFFFu, c[nt][2], srcA);
                float x3 = __shfl_sync(0xFFFFFFFFu, c[nt][3], srcA);
                float y0 = __shfl_sync(0xFFFFFFFFu, c[nt][0], srcA + 2);
                float y1 = __shfl_sync(0xFFFFFFFFu, c[nt][1], srcA + 2);
                float y2 = __shfl_sync(0xFFFFFFFFu, c[nt][2], srcA + 2);
                float y3 = __shfl_sync(0xFFFFFFFFu, c[nt][3], srcA + 2);
                unsigned a[4];
                a[0] = f2tf32(par ? x1 : x0);
                a[1] = f2tf32(par ? x3 : x2);
                a[2] = f2tf32(par ? y1 : y0);
                a[3] = f2tf32(par ? y3 : y2);
                unsigned b0[2] = { Vu[g * 260 + k0 + tig], Vu[g * 260 + k0 + tig + 4] };
                mma_tf32(o0, a, b0);
                unsigned b1[2] = { Vu[(8 + g) * 260 + k0 + tig], Vu[(8 + g) * 260 + k0 + tig + 4] };
                mma_tf32(o1, a, b1);
            }
            *(float2*)&Os[nq * 576 + (mrow + g) * 18 + tig * 2]         = make_float2(o0[0], o0[1]);
            *(float2*)&Os[nq * 576 + (mrow + 8 + g) * 18 + tig * 2]     = make_float2(o0[2], o0[3]);
            *(float2*)&Os[nq * 576 + (mrow + g) * 18 + 8 + tig * 2]     = make_float2(o1[0], o1[1]);
            *(float2*)&Os[nq * 576 + (mrow + 8 + g) * 18 + 8 + tig * 2] = make_float2(o1[2], o1[3]);
        }
        __syncthreads();

        // ---- reduce 4 nq partials, write out_win [win][c][m] coalesced ----
        {
            float* outw = g_q1;
#pragma unroll
            for (int i = 0; i < 2; i++) {
                int e = i * 256 + t;
                int m = e & 31, d = e >> 5;
                float s = Os[m * 18 + d] + Os[576 + m * 18 + d]
                        + Os[1152 + m * 18 + d] + Os[1728 + m * 18 + d];
                outw[((size_t)win * 128 + head * 16 + d) * 256 + m0 + m] = s;
            }
        }
        __syncthreads();   // protect Os + RED buffers before next tile
    }
}

// =====================================================================================
// K4: window reverse for `out`: out_win [win][c][m] -> NCHW (unchanged)
// =====================================================================================
__global__ void k4_winrev(float* __restrict__ outp)
{
    __shared__ float s[16 * 272];
    int a = blockIdx.x;
    int c = blockIdx.y;
    int t = threadIdx.x;
    int g = t >> 4, bcol = t & 15;

    const float* outw = g_q1;
    for (int j = 0; j < 16; j++) {
        float v = outw[((size_t)(j * 16 + g) * 128 + c) * 256 + a * 16 + bcol];
        int col = bcol * 16 + g;
        s[j * 272 + col + (col >> 4)] = v;
    }
    __syncthreads();
    for (int j = 0; j < 16; j++) {
        int col = t;
        outp[(size_t)c * 65536 + (a * 16 + j) * 256 + t] = s[j * 272 + col + (col >> 4)];
    }
}

// =====================================================================================
extern "C" void kernel_launch(void* const* d_in, const int* in_sizes, int n_in,
                              void* d_out, int out_size)
{
    const float* lms   = (const float*)d_in[0];
    const float* pan   = (const float*)d_in[1];
    const float* gms   = (const float*)d_in[2];
    const float* gpan  = (const float*)d_in[3];
    const float* qw1   = (const float*)d_in[4];
    const float* qb1   = (const float*)d_in[5];
    const float* qw2   = (const float*)d_in[6];
    const float* qb2   = (const float*)d_in[7];
    const float* kvw1  = (const float*)d_in[8];
    const float* kvb1  = (const float*)d_in[9];
    const float* kvw2  = (const float*)d_in[10];
    const float* kvb2  = (const float*)d_in[11];

    float* attn = (float*)d_out;                   // (256, 8, 256, 256)
    float* outp = attn + 134217728;                // (1, 128, 256, 256)

    cudaFuncSetAttribute(k1_ln_conv1, cudaFuncAttributeMaxDynamicSharedMemorySize, 69632);
    cudaFuncSetAttribute(k3_attn_mma, cudaFuncAttributeMaxDynamicSharedMemorySize, 43840);

    k1_ln_conv1<<<512, 256, 69632>>>(lms, pan, gms, gpan, qw1, qb1, kvw1, kvb1);
    k2_dwconv_scatter<<<dim3(16, 384), 256>>>(qw2, qb2, kvw2, kvb2);
    k3_attn_mma<<<dim3(8, 256), 256, 43840>>>(attn);
    k4_winrev<<<dim3(16, 128), 256>>>(outp);
}

// round 10
// speedup vs baseline: 2.8426x; 1.0369x over previous
#include <cuda_runtime.h>
#include <math.h>

// ---------------- scratch (device globals; no allocations allowed) ----------------
__device__ float g_q1[128u * 65536u];          // 32 MB : conv1 q output (NCHW), later out_win
__device__ float g_kv1[256u * 65536u];         // 64 MB : conv1 kv output (NCHW)
__device__ float g_qw[256u * 128u * 256u];     // 32 MB : q  in [win][c][m]
__device__ float g_kw[256u * 128u * 256u];     // 32 MB : k  in [win][c][m]
__device__ float g_vw[256u * 128u * 256u];     // 32 MB : v  in [win][c][m]

// =====================================================================================
// helpers
// =====================================================================================
__device__ __forceinline__ unsigned f2tf32(float f) {
    unsigned u;
    asm("cvt.rna.tf32.f32 %0, %1;" : "=r"(u) : "f"(f));
    return u;
}
__device__ __forceinline__ void mma_tf32(float c[4], const unsigned a[4], const unsigned b[2]) {
    asm volatile(
        "mma.sync.aligned.m16n8k8.row.col.f32.tf32.tf32.f32 "
        "{%0,%1,%2,%3},{%4,%5,%6,%7},{%8,%9},{%0,%1,%2,%3};"
        : "+f"(c[0]), "+f"(c[1]), "+f"(c[2]), "+f"(c[3])
        : "r"(a[0]), "r"(a[1]), "r"(a[2]), "r"(a[3]), "r"(b[0]), "r"(b[1]));
}

// =====================================================================================
// K1: LN + 1x1 convs as tf32 tensor GEMM with x hi/lo compensation. (unchanged)
// =====================================================================================
__global__ void __launch_bounds__(256, 2) k1_ln_conv1(
    const float* __restrict__ lms, const float* __restrict__ pan,
    const float* __restrict__ gms, const float* __restrict__ gpan,
    const float* __restrict__ qw1, const float* __restrict__ qb1,
    const float* __restrict__ kvw1, const float* __restrict__ kvb1)
{
    extern __shared__ float sw[];
    unsigned* Xh = (unsigned*)sw;            // 64 x 136
    unsigned* Xl = (unsigned*)(sw + 8704);   // 64 x 136

    int t = threadIdx.x;
    int lane = t & 31, w = t >> 5;
    int g = lane >> 2, tig = lane & 3;
    int p0 = blockIdx.x * 128;

    unsigned a[3][4][4];
    float bias0[3], bias1[3];
#pragma unroll
    for (int j = 0; j < 3; j++) {
        int R = j * 128 + w * 16;
        const float* Wsrc = (j == 0) ? qw1 : kvw1;
        int r0 = (j == 0) ? R : (R - 128);
#pragma unroll
        for (int ks = 0; ks < 4; ks++) {
            int k0 = ks * 8;
            a[j][ks][0] = f2tf32(Wsrc[(r0 + g) * 32 + k0 + tig]);
            a[j][ks][1] = f2tf32(Wsrc[(r0 + 8 + g) * 32 + k0 + tig]);
            a[j][ks][2] = f2tf32(Wsrc[(r0 + g) * 32 + k0 + tig + 4]);
            a[j][ks][3] = f2tf32(Wsrc[(r0 + 8 + g) * 32 + k0 + tig + 4]);
        }
        const float* Bsrc = (j == 0) ? qb1 : kvb1;
        bias0[j] = Bsrc[r0 + g];
        bias1[j] = Bsrc[r0 + 8 + g];
    }

    {
        int which = t >> 7;
        int px = t & 127;
        const float* src = which ? lms : pan;
        const float* gg  = which ? gms : gpan;
        float x[32];
        float s = 0.f, s2 = 0.f;
#pragma unroll
        for (int i = 0; i < 32; i++) {
            float v = src[i * 65536 + p0 + px];
            x[i] = v; s += v; s2 += v * v;
        }
        float m = s * (1.f / 32.f);
        float var = s2 * (1.f / 32.f) - m * m;
        float r = rsqrtf(var + 1e-5f);
#pragma unroll
        for (int i = 0; i < 32; i++) {
            float xn = (x[i] - m) * r * gg[i];
            unsigned xh = f2tf32(xn);
            unsigned xl = f2tf32(xn - __uint_as_float(xh));
            int row = which * 32 + i;
            Xh[row * 136 + px] = xh;
            Xl[row * 136 + px] = xl;
        }
    }
    __syncthreads();

    for (int nt = 0; nt < 16; nt++) {
        int n0 = nt * 8;
#pragma unroll
        for (int j = 0; j < 3; j++) {
            int xrow = (j > 0) ? 32 : 0;
            float c[4] = {bias0[j], bias0[j], bias1[j], bias1[j]};
#pragma unroll
            for (int ks = 0; ks < 4; ks++) {
                int k0 = ks * 8;
                unsigned bh[2] = { Xh[(xrow + k0 + tig) * 136 + n0 + g],
                                   Xh[(xrow + k0 + tig + 4) * 136 + n0 + g] };
                mma_tf32(c, a[j][ks], bh);
                unsigned bl[2] = { Xl[(xrow + k0 + tig) * 136 + n0 + g],
                                   Xl[(xrow + k0 + tig + 4) * 136 + n0 + g] };
                mma_tf32(c, a[j][ks], bl);
            }
            int R = j * 128 + w * 16;
            int px = p0 + n0 + tig * 2;
            int row0 = R + g, row1 = R + 8 + g;
            float* d0 = (row0 < 128) ? (g_q1 + (size_t)row0 * 65536)
                                     : (g_kv1 + (size_t)(row0 - 128) * 65536);
            float* d1 = (row1 < 128) ? (g_q1 + (size_t)row1 * 65536)
                                     : (g_kv1 + (size_t)(row1 - 128) * 65536);
            *(float2*)&d0[px] = make_float2(c[0], c[1]);
            *(float2*)&d1[px] = make_float2(c[2], c[3]);
        }
    }
}

// =====================================================================================
// K2: depthwise 3x3 (SAME) + dilated-window scatter. (unchanged)
// =====================================================================================
#define SK18(r, c) ((r) * 272 + (c) + ((c) >> 4))

__global__ void k2_dwconv_scatter(const float* __restrict__ qw2, const float* __restrict__ qb2,
                                  const float* __restrict__ kvw2, const float* __restrict__ kvb2)
{
    __shared__ float s[18 * 272];
    int c = blockIdx.y;
    int a = blockIdx.x;
    int h0 = a * 16;
    int t = threadIdx.x;

    const float* src; float* dst; int dstc; const float* wsrc; const float* bsrc; int cw;
    if (c < 128)      { src = g_q1  + (size_t)c * 65536;         dst = g_qw; dstc = c;        wsrc = qw2;  bsrc = qb2;  cw = c; }
    else {
        int ck = c - 128;
        src = g_kv1 + (size_t)ck * 65536;
        wsrc = kvw2; bsrc = kvb2; cw = ck;
        if (ck < 128) { dst = g_kw; dstc = ck; }
        else          { dst = g_vw; dstc = ck - 128; }
    }

    float w9[9];
#pragma unroll
    for (int j = 0; j < 9; j++) w9[j] = wsrc[cw * 9 + j];
    float bias = bsrc[cw];

    for (int i = t; i < 18 * 256; i += 256) {
        int rr = i >> 8, ww = i & 255;
        int h = h0 - 1 + rr;
        float v = (h >= 0 && h < 256) ? src[h * 256 + ww] : 0.f;
        s[SK18(rr, ww)] = v;
    }
    __syncthreads();

    int g = t >> 4, bcol = t & 15;
    for (int j = 0; j < 16; j++) {
        int hh = j, wx = g;
        int wpix = bcol * 16 + wx;
        float acc = bias;
#pragma unroll
        for (int dy = 0; dy < 3; dy++) {
#pragma unroll
            for (int dx = 0; dx < 3; dx++) {
                int ww = wpix + dx - 1;
                float v = (ww >= 0 && ww < 256) ? s[SK18(hh + dy, ww)] : 0.f;
                acc += w9[dy * 3 + dx] * v;
            }
        }
        int win = hh * 16 + wx;
        dst[((size_t)win * 128 + dstc) * 256 + a * 16 + bcol] = acc;
    }
}

// =====================================================================================
// K3: attention, one block per (head, win), 256 threads, register-resident probs.
//   R9 changes: launch_bounds (256,3) -> ~85 regs (kill spills from the 64-reg cap);
//   Q A-frag loads for tile mq+1 prefetched into regs right after tile mq's QK MMAs.
//   smem: Ks 16x264 | Vs 16x260 | Os 4x32x18 | REDM/REDS 128+128 | RN 16 = 43840 B
// =====================================================================================
__global__ void __launch_bounds__(256, 3) k3_attn_mma(float* __restrict__ attn)
{
    extern __shared__ float sm[];
    float* Ks   = sm;                    // 4224
    float* Vs   = sm + 4224;             // 4160
    float* Os   = sm + 8384;             // 2304 (4 nq x 32 x 18)
    float* REDM = sm + 10688;            // 128
    float* REDS = sm + 10816;            // 128
    float* RN   = sm + 10944;            // 16

    unsigned* Ku = (unsigned*)Ks;
    unsigned* Vu = (unsigned*)Vs;

    int t    = threadIdx.x;
    int lane = t & 31, wid = t >> 5;
    int g    = lane >> 2, tig = lane & 3;
    int head = blockIdx.x;
    int win  = blockIdx.y;

    const float* qb = g_qw + ((size_t)win * 128 + head * 16) * 256;
    const float* kb = g_kw + ((size_t)win * 128 + head * 16) * 256;
    const float* vb = g_vw + ((size_t)win * 128 + head * 16) * 256;

    // ---- stage K (regs) + V (tf32 smem) ----
    float kreg[16];
#pragma unroll
    for (int d = 0; d < 16; d++) kreg[d] = kb[d * 256 + t];
#pragma unroll
    for (int d = 0; d < 16; d++) Vu[d * 260 + t] = f2tf32(vb[d * 256 + t]);

    // ---- k norm over tokens per channel d ----
#pragma unroll
    for (int d = 0; d < 16; d++) {
        float ssq = kreg[d] * kreg[d];
#pragma unroll
        for (int off = 16; off > 0; off >>= 1) ssq += __shfl_xor_sync(0xFFFFFFFFu, ssq, off);
        if (lane == 0) REDM[d * 8 + wid] = ssq;
    }
    __syncthreads();
    if (t < 16) {
        float s = 0.f;
#pragma unroll
        for (int j = 0; j < 8; j++) s += REDM[t * 8 + j];
        RN[t] = 1.f / fmaxf(sqrtf(s), 1e-12f);
    }
    __syncthreads();
#pragma unroll
    for (int d = 0; d < 16; d++) Ku[d * 264 + t] = f2tf32(kreg[d] * RN[d]);
    __syncthreads();

    int mt = wid >> 2, nq = wid & 3;     // warp role, fixed across tiles
    int mrow = mt * 16;
    int srcA = (lane & 0x1C) + (tig >> 1);  // C->A shuffle source (col tig)
    int par  = tig & 1;

    // ---- prefetch Q A-frag rows for tile 0 ----
    float qn[8];
    {
        const float* qrow = qb + mrow;
#pragma unroll
        for (int ks = 0; ks < 2; ks++) {
            int k0 = ks * 8;
            qn[ks * 4 + 0] = qrow[(k0 + tig) * 256 + g];
            qn[ks * 4 + 1] = qrow[(k0 + tig) * 256 + 8 + g];
            qn[ks * 4 + 2] = qrow[(k0 + tig + 4) * 256 + g];
            qn[ks * 4 + 3] = qrow[(k0 + tig + 4) * 256 + 8 + g];
        }
    }

    for (int mq = 0; mq < 8; mq++) {
        int m0 = mq * 32;

        // ---- QK: m16 x n64 per warp, K=16; A-frags from prefetched regs ----
        float c[8][4];
        {
            unsigned a[2][4];
#pragma unroll
            for (int ks = 0; ks < 2; ks++)
#pragma unroll
                for (int i = 0; i < 4; i++) a[ks][i] = f2tf32(qn[ks * 4 + i]);
#pragma unroll
            for (int nt = 0; nt < 8; nt++) {
                int n0 = nq * 64 + nt * 8;
                c[nt][0] = 0.f; c[nt][1] = 0.f; c[nt][2] = 0.f; c[nt][3] = 0.f;
#pragma unroll
                for (int ks = 0; ks < 2; ks++) {
                    int k0 = ks * 8;
                    unsigned b[2] = { Ku[(k0 + tig) * 264 + n0 + g],
                                      Ku[(k0 + tig + 4) * 264 + n0 + g] };
                    mma_tf32(c[nt], a[ks], b);
                }
            }
        }

        // ---- prefetch next tile's Q (overlaps softmax + stores + AV) ----
        if (mq < 7) {
            const float* qrow = qb + (mq + 1) * 32 + mrow;
#pragma unroll
            for (int ks = 0; ks < 2; ks++) {
                int k0 = ks * 8;
                qn[ks * 4 + 0] = qrow[(k0 + tig) * 256 + g];
                qn[ks * 4 + 1] = qrow[(k0 + tig) * 256 + 8 + g];
                qn[ks * 4 + 2] = qrow[(k0 + tig + 4) * 256 + g];
                qn[ks * 4 + 3] = qrow[(k0 + tig + 4) * 256 + 8 + g];
            }
        }

        // ---- softmax, fused. rows rA = mrow+g, rB = mrow+8+g ----
        int rA = mrow + g, rB = mrow + 8 + g;
        {
            float mA = -3.0e38f, mB = -3.0e38f;
#pragma unroll
            for (int nt = 0; nt < 8; nt++) {
                mA = fmaxf(mA, fmaxf(c[nt][0], c[nt][1]));
                mB = fmaxf(mB, fmaxf(c[nt][2], c[nt][3]));
            }
            mA = fmaxf(mA, __shfl_xor_sync(0xFFFFFFFFu, mA, 1));
            mA = fmaxf(mA, __shfl_xor_sync(0xFFFFFFFFu, mA, 2));
            mB = fmaxf(mB, __shfl_xor_sync(0xFFFFFFFFu, mB, 1));
            mB = fmaxf(mB, __shfl_xor_sync(0xFFFFFFFFu, mB, 2));
            if (tig == 0) { REDM[rA * 4 + nq] = mA; REDM[rB * 4 + nq] = mB; }
        }
        __syncthreads();
        {
            float mA = fmaxf(fmaxf(REDM[rA * 4], REDM[rA * 4 + 1]),
                             fmaxf(REDM[rA * 4 + 2], REDM[rA * 4 + 3]));
            float mB = fmaxf(fmaxf(REDM[rB * 4], REDM[rB * 4 + 1]),
                             fmaxf(REDM[rB * 4 + 2], REDM[rB * 4 + 3]));
            float sA = 0.f, sB = 0.f;
#pragma unroll
            for (int nt = 0; nt < 8; nt++) {
                c[nt][0] = __expf(c[nt][0] - mA); c[nt][1] = __expf(c[nt][1] - mA);
                c[nt][2] = __expf(c[nt][2] - mB); c[nt][3] = __expf(c[nt][3] - mB);
                sA += c[nt][0] + c[nt][1];
                sB += c[nt][2] + c[nt][3];
            }
            sA += __shfl_xor_sync(0xFFFFFFFFu, sA, 1);
            sA += __shfl_xor_sync(0xFFFFFFFFu, sA, 2);
            sB += __shfl_xor_sync(0xFFFFFFFFu, sB, 1);
            sB += __shfl_xor_sync(0xFFFFFFFFu, sB, 2);
            if (tig == 0) { REDS[rA * 4 + nq] = sA; REDS[rB * 4 + nq] = sB; }
        }
        __syncthreads();
        {
            float rinvA = 1.f / (REDS[rA * 4] + REDS[rA * 4 + 1] + REDS[rA * 4 + 2] + REDS[rA * 4 + 3]);
            float rinvB = 1.f / (REDS[rB * 4] + REDS[rB * 4 + 1] + REDS[rB * 4 + 2] + REDS[rB * 4 + 3]);
            float* oA = attn + ((size_t)((win * 8 + head) * 256 + m0 + rA)) * 256;
            float* oB = attn + ((size_t)((win * 8 + head) * 256 + m0 + rB)) * 256;
#pragma unroll
            for (int nt = 0; nt < 8; nt++) {
                int n0 = nq * 64 + nt * 8 + tig * 2;
                c[nt][0] *= rinvA; c[nt][1] *= rinvA;
                c[nt][2] *= rinvB; c[nt][3] *= rinvB;
                __stcs((float2*)&oA[n0], make_float2(c[nt][0], c[nt][1]));
                __stcs((float2*)&oB[n0], make_float2(c[nt][2], c[nt][3]));
            }
        }

        // ---- AV: P (regs, via C->A shuffle) x V (smem). O partial m16 x d16 ----
        {
            float o0[4] = {0.f, 0.f, 0.f, 0.f};   // d 0..7
            float o1[4] = {0.f, 0.f, 0.f, 0.f};   // d 8..15
#pragma unroll
            for (int nt = 0; nt < 8; nt++) {
                int k0 = nq * 64 + nt * 8;
                float x0 = __shfl_sync(0xFFFFFFFFu, c[nt][0], srcA);
                float x1 = __shfl_sync(0xFFFFFFFFu, c[nt][1], srcA);
                float x2 = __shfl_sync(0xFFFFFFFFu, c[nt][2], srcA);
                float x3 = __shfl_sync(0xFFFFFFFFu, c[nt][3], srcA);
                float y0 = __shfl_sync(0xFFFFFFFFu, c[nt][0], srcA + 2);
                float y1 = __shfl_sync(0xFFFFFFFFu, c[nt][1], srcA + 2);
                float y2 = __shfl_sync(0xFFFFFFFFu, c[nt][2], srcA + 2);
                float y3 = __shfl_sync(0xFFFFFFFFu, c[nt][3], srcA + 2);
                unsigned a[4];
                a[0] = f2tf32(par ? x1 : x0);
                a[1] = f2tf32(par ? x3 : x2);
                a[2] = f2tf32(par ? y1 : y0);
                a[3] = f2tf32(par ? y3 : y2);
                unsigned b0[2] = { Vu[g * 260 + k0 + tig], Vu[g * 260 + k0 + tig + 4] };
                mma_tf32(o0, a, b0);
                unsigned b1[2] = { Vu[(8 + g) * 260 + k0 + tig], Vu[(8 + g) * 260 + k0 + tig + 4] };
                mma_tf32(o1, a, b1);
            }
            *(float2*)&Os[nq * 576 + (mrow + g) * 18 + tig * 2]         = make_float2(o0[0], o0[1]);
            *(float2*)&Os[nq * 576 + (mrow + 8 + g) * 18 + tig * 2]     = make_float2(o0[2], o0[3]);
            *(float2*)&Os[nq * 576 + (mrow + g) * 18 + 8 + tig * 2]     = make_float2(o1[0], o1[1]);
            *(float2*)&Os[nq * 576 + (mrow + 8 + g) * 18 + 8 + tig * 2] = make_float2(o1[2], o1[3]);
        }
        __syncthreads();

        // ---- reduce 4 nq partials, write out_win [win][c][m] coalesced ----
        {
            float* outw = g_q1;
#pragma unroll
            for (int i = 0; i < 2; i++) {
                int e = i * 256 + t;
                int m = e & 31, d = e >> 5;
                float s = Os[m * 18 + d] + Os[576 + m * 18 + d]
                        + Os[1152 + m * 18 + d] + Os[1728 + m * 18 + d];
                outw[((size_t)win * 128 + head * 16 + d) * 256 + m0 + m] = s;
            }
        }
        __syncthreads();   // protect Os + RED buffers before next tile
    }
}

// =====================================================================================
// K4: window reverse for `out`: out_win [win][c][m] -> NCHW (unchanged)
// =====================================================================================
__global__ void k4_winrev(float* __restrict__ outp)
{
    __shared__ float s[16 * 272];
    int a = blockIdx.x;
    int c = blockIdx.y;
    int t = threadIdx.x;
    int g = t >> 4, bcol = t & 15;

    const float* outw = g_q1;
    for (int j = 0; j < 16; j++) {
        float v = outw[((size_t)(j * 16 + g) * 128 + c) * 256 + a * 16 + bcol];
        int col = bcol * 16 + g;
        s[j * 272 + col + (col >> 4)] = v;
    }
    __syncthreads();
    for (int j = 0; j < 16; j++) {
        int col = t;
        outp[(size_t)c * 65536 + (a * 16 + j) * 256 + t] = s[j * 272 + col + (col >> 4)];
    }
}

// =====================================================================================
extern "C" void kernel_launch(void* const* d_in, const int* in_sizes, int n_in,
                              void* d_out, int out_size)
{
    const float* lms   = (const float*)d_in[0];
    const float* pan   = (const float*)d_in[1];
    const float* gms   = (const float*)d_in[2];
    const float* gpan  = (const float*)d_in[3];
    const float* qw1   = (const float*)d_in[4];
    const float* qb1   = (const float*)d_in[5];
    const float* qw2   = (const float*)d_in[6];
    const float* qb2   = (const float*)d_in[7];
    const float* kvw1  = (const float*)d_in[8];
    const float* kvb1  = (const float*)d_in[9];
    const float* kvw2  = (const float*)d_in[10];
    const float* kvb2  = (const float*)d_in[11];

    float* attn = (float*)d_out;                   // (256, 8, 256, 256)
    float* outp = attn + 134217728;                // (1, 128, 256, 256)

    cudaFuncSetAttribute(k1_ln_conv1, cudaFuncAttributeMaxDynamicSharedMemorySize, 69632);
    cudaFuncSetAttribute(k3_attn_mma, cudaFuncAttributeMaxDynamicSharedMemorySize, 43840);

    k1_ln_conv1<<<512, 256, 69632>>>(lms, pan, gms, gpan, qw1, qb1, kvw1, kvb1);
    k2_dwconv_scatter<<<dim3(16, 384), 256>>>(qw2, qb2, kvw2, kvb2);
    k3_attn_mma<<<dim3(8, 256), 256, 43840>>>(attn);
    k4_winrev<<<dim3(16, 128), 256>>>(outp);
}

// round 12
// speedup vs baseline: 2.9325x; 1.0316x over previous
#include <cuda_runtime.h>
#include <math.h>

// ---------------- scratch (device globals; no allocations allowed) ----------------
__device__ float g_q1[128u * 65536u];          // 32 MB : conv1 q output (NCHW), later out_win
__device__ float g_kv1[256u * 65536u];         // 64 MB : conv1 kv output (NCHW)
__device__ float g_qw[256u * 128u * 256u];     // 32 MB : q  in [win][c][m]
__device__ float g_kw[256u * 128u * 256u];     // 32 MB : k  in [win][c][m]
__device__ float g_vw[256u * 128u * 256u];     // 32 MB : v  in [win][c][m]

// =====================================================================================
// helpers
// =====================================================================================
__device__ __forceinline__ unsigned f2tf32(float f) {
    unsigned u;
    asm("cvt.rna.tf32.f32 %0, %1;" : "=r"(u) : "f"(f));
    return u;
}
__device__ __forceinline__ void mma_tf32(float c[4], const unsigned a[4], const unsigned b[2]) {
    asm volatile(
        "mma.sync.aligned.m16n8k8.row.col.f32.tf32.tf32.f32 "
        "{%0,%1,%2,%3},{%4,%5,%6,%7},{%8,%9},{%0,%1,%2,%3};"
        : "+f"(c[0]), "+f"(c[1]), "+f"(c[2]), "+f"(c[3])
        : "r"(a[0]), "r"(a[1]), "r"(a[2]), "r"(a[3]), "r"(b[0]), "r"(b[1]));
}

// =====================================================================================
// K1: LN + 1x1 convs as tf32 tensor GEMM with x hi/lo compensation. (unchanged)
// =====================================================================================
__global__ void __launch_bounds__(256, 2) k1_ln_conv1(
    const float* __restrict__ lms, const float* __restrict__ pan,
    const float* __restrict__ gms, const float* __restrict__ gpan,
    const float* __restrict__ qw1, const float* __restrict__ qb1,
    const float* __restrict__ kvw1, const float* __restrict__ kvb1)
{
    extern __shared__ float sw[];
    unsigned* Xh = (unsigned*)sw;            // 64 x 136
    unsigned* Xl = (unsigned*)(sw + 8704);   // 64 x 136

    int t = threadIdx.x;
    int lane = t & 31, w = t >> 5;
    int g = lane >> 2, tig = lane & 3;
    int p0 = blockIdx.x * 128;

    unsigned a[3][4][4];
    float bias0[3], bias1[3];
#pragma unroll
    for (int j = 0; j < 3; j++) {
        int R = j * 128 + w * 16;
        const float* Wsrc = (j == 0) ? qw1 : kvw1;
        int r0 = (j == 0) ? R : (R - 128);
#pragma unroll
        for (int ks = 0; ks < 4; ks++) {
            int k0 = ks * 8;
            a[j][ks][0] = f2tf32(Wsrc[(r0 + g) * 32 + k0 + tig]);
            a[j][ks][1] = f2tf32(Wsrc[(r0 + 8 + g) * 32 + k0 + tig]);
            a[j][ks][2] = f2tf32(Wsrc[(r0 + g) * 32 + k0 + tig + 4]);
            a[j][ks][3] = f2tf32(Wsrc[(r0 + 8 + g) * 32 + k0 + tig + 4]);
        }
        const float* Bsrc = (j == 0) ? qb1 : kvb1;
        bias0[j] = Bsrc[r0 + g];
        bias1[j] = Bsrc[r0 + 8 + g];
    }

    {
        int which = t >> 7;
        int px = t & 127;
        const float* src = which ? lms : pan;
        const float* gg  = which ? gms : gpan;
        float x[32];
        float s = 0.f, s2 = 0.f;
#pragma unroll
        for (int i = 0; i < 32; i++) {
            float v = src[i * 65536 + p0 + px];
            x[i] = v; s += v; s2 += v * v;
        }
        float m = s * (1.f / 32.f);
        float var = s2 * (1.f / 32.f) - m * m;
        float r = rsqrtf(var + 1e-5f);
#pragma unroll
        for (int i = 0; i < 32; i++) {
            float xn = (x[i] - m) * r * gg[i];
            unsigned xh = f2tf32(xn);
            unsigned xl = f2tf32(xn - __uint_as_float(xh));
            int row = which * 32 + i;
            Xh[row * 136 + px] = xh;
            Xl[row * 136 + px] = xl;
        }
    }
    __syncthreads();

    for (int nt = 0; nt < 16; nt++) {
        int n0 = nt * 8;
#pragma unroll
        for (int j = 0; j < 3; j++) {
            int xrow = (j > 0) ? 32 : 0;
            float c[4] = {bias0[j], bias0[j], bias1[j], bias1[j]};
#pragma unroll
            for (int ks = 0; ks < 4; ks++) {
                int k0 = ks * 8;
                unsigned bh[2] = { Xh[(xrow + k0 + tig) * 136 + n0 + g],
                                   Xh[(xrow + k0 + tig + 4) * 136 + n0 + g] };
                mma_tf32(c, a[j][ks], bh);
                unsigned bl[2] = { Xl[(xrow + k0 + tig) * 136 + n0 + g],
                                   Xl[(xrow + k0 + tig + 4) * 136 + n0 + g] };
                mma_tf32(c, a[j][ks], bl);
            }
            int R = j * 128 + w * 16;
            int px = p0 + n0 + tig * 2;
            int row0 = R + g, row1 = R + 8 + g;
            float* d0 = (row0 < 128) ? (g_q1 + (size_t)row0 * 65536)
                                     : (g_kv1 + (size_t)(row0 - 128) * 65536);
            float* d1 = (row1 < 128) ? (g_q1 + (size_t)row1 * 65536)
                                     : (g_kv1 + (size_t)(row1 - 128) * 65536);
            *(float2*)&d0[px] = make_float2(c[0], c[1]);
            *(float2*)&d1[px] = make_float2(c[2], c[3]);
        }
    }
}

// =====================================================================================
// K2: depthwise 3x3 (SAME) + dilated-window scatter. (unchanged)
// =====================================================================================
#define SK18(r, c) ((r) * 272 + (c) + ((c) >> 4))

__global__ void k2_dwconv_scatter(const float* __restrict__ qw2, const float* __restrict__ qb2,
                                  const float* __restrict__ kvw2, const float* __restrict__ kvb2)
{
    __shared__ float s[18 * 272];
    int c = blockIdx.y;
    int a = blockIdx.x;
    int h0 = a * 16;
    int t = threadIdx.x;

    const float* src; float* dst; int dstc; const float* wsrc; const float* bsrc; int cw;
    if (c < 128)      { src = g_q1  + (size_t)c * 65536;         dst = g_qw; dstc = c;        wsrc = qw2;  bsrc = qb2;  cw = c; }
    else {
        int ck = c - 128;
        src = g_kv1 + (size_t)ck * 65536;
        wsrc = kvw2; bsrc = kvb2; cw = ck;
        if (ck < 128) { dst = g_kw; dstc = ck; }
        else          { dst = g_vw; dstc = ck - 128; }
    }

    float w9[9];
#pragma unroll
    for (int j = 0; j < 9; j++) w9[j] = wsrc[cw * 9 + j];
    float bias = bsrc[cw];

    for (int i = t; i < 18 * 256; i += 256) {
        int rr = i >> 8, ww = i & 255;
        int h = h0 - 1 + rr;
        float v = (h >= 0 && h < 256) ? src[h * 256 + ww] : 0.f;
        s[SK18(rr, ww)] = v;
    }
    __syncthreads();

    int g = t >> 4, bcol = t & 15;
    for (int j = 0; j < 16; j++) {
        int hh = j, wx = g;
        int wpix = bcol * 16 + wx;
        float acc = bias;
#pragma unroll
        for (int dy = 0; dy < 3; dy++) {
#pragma unroll
            for (int dx = 0; dx < 3; dx++) {
                int ww = wpix + dx - 1;
                float v = (ww >= 0 && ww < 256) ? s[SK18(hh + dy, ww)] : 0.f;
                acc += w9[dy * 3 + dx] * v;
            }
        }
        int win = hh * 16 + wx;
        dst[((size_t)win * 128 + dstc) * 256 + a * 16 + bcol] = acc;
    }
}

// =====================================================================================
// K3: attention, one block per (head, win), 256 threads, register-resident probs.
//   R10: no max-subtraction (logits |x| <= ~0.03, softmax shift-invariant);
//   k-norm folded into Q A-frags (K straight to tf32 smem during staging);
//   2 block barriers per tile (REDS-sum, Os partials) - others proven redundant.
//   smem: Ks 16x264 | Vs 16x260 | Os 4x32x18 | REDS 128 | RN 16 = 43328 B
// =====================================================================================
__global__ void __launch_bounds__(256, 3) k3_attn_mma(float* __restrict__ attn)
{
    extern __shared__ float sm[];
    float* Ks   = sm;                    // 4224
    float* Vs   = sm + 4224;             // 4160
    float* Os   = sm + 8384;             // 2304 (4 nq x 32 x 18)
    float* REDS = sm + 10688;            // 128 (also ssq scratch pre-loop)
    float* RN   = sm + 10816;            // 16

    unsigned* Ku = (unsigned*)Ks;
    unsigned* Vu = (unsigned*)Vs;

    int t    = threadIdx.x;
    int lane = t & 31, wid = t >> 5;
    int g    = lane >> 2, tig = lane & 3;
    int head = blockIdx.x;
    int win  = blockIdx.y;

    const float* qb = g_qw + ((size_t)win * 128 + head * 16) * 256;
    const float* kb = g_kw + ((size_t)win * 128 + head * 16) * 256;
    const float* vb = g_vw + ((size_t)win * 128 + head * 16) * 256;

    // ---- stage K (tf32 smem, unnormalized) + ssq partials in the same pass; V tf32 ----
#pragma unroll
    for (int d = 0; d < 16; d++) {
        float kv = kb[d * 256 + t];
        Ku[d * 264 + t] = f2tf32(kv);
        float ssq = kv * kv;
#pragma unroll
        for (int off = 16; off > 0; off >>= 1) ssq += __shfl_xor_sync(0xFFFFFFFFu, ssq, off);
        if (lane == 0) REDS[d * 8 + wid] = ssq;
    }
#pragma unroll
    for (int d = 0; d < 16; d++) Vu[d * 260 + t] = f2tf32(vb[d * 256 + t]);
    __syncthreads();
    if (t < 16) {
        float s = 0.f;
#pragma unroll
        for (int j = 0; j < 8; j++) s += REDS[t * 8 + j];
        RN[t] = 1.f / fmaxf(sqrtf(s), 1e-12f);
    }
    __syncthreads();

    int mt = wid >> 2, nq = wid & 3;     // warp role, fixed across tiles
    int mrow = mt * 16;
    int srcA = (lane & 0x1C) + (tig >> 1);  // C->A shuffle source (col tig)
    int par  = tig & 1;

    // per-thread k-norm scales for the Q A-frag d-rows
    float rnv[4] = { RN[tig], RN[tig + 4], RN[8 + tig], RN[8 + tig + 4] };

    // ---- prefetch Q A-frag rows for tile 0 ----
    float qn[8];
    {
        const float* qrow = qb + mrow;
#pragma unroll
        for (int ks = 0; ks < 2; ks++) {
            int k0 = ks * 8;
            qn[ks * 4 + 0] = qrow[(k0 + tig) * 256 + g];
            qn[ks * 4 + 1] = qrow[(k0 + tig) * 256 + 8 + g];
            qn[ks * 4 + 2] = qrow[(k0 + tig + 4) * 256 + g];
            qn[ks * 4 + 3] = qrow[(k0 + tig + 4) * 256 + 8 + g];
        }
    }

    for (int mq = 0; mq < 8; mq++) {
        int m0 = mq * 32;

        // ---- QK: m16 x n64 per warp, K=16; A-frags = prefetched q * rn ----
        float c[8][4];
        {
            unsigned a[2][4];
#pragma unroll
            for (int ks = 0; ks < 2; ks++) {
                a[ks][0] = f2tf32(qn[ks * 4 + 0] * rnv[ks * 2 + 0]);
                a[ks][1] = f2tf32(qn[ks * 4 + 1] * rnv[ks * 2 + 0]);
                a[ks][2] = f2tf32(qn[ks * 4 + 2] * rnv[ks * 2 + 1]);
                a[ks][3] = f2tf32(qn[ks * 4 + 3] * rnv[ks * 2 + 1]);
            }
#pragma unroll
            for (int nt = 0; nt < 8; nt++) {
                int n0 = nq * 64 + nt * 8;
                c[nt][0] = 0.f; c[nt][1] = 0.f; c[nt][2] = 0.f; c[nt][3] = 0.f;
#pragma unroll
                for (int ks = 0; ks < 2; ks++) {
                    int k0 = ks * 8;
                    unsigned b[2] = { Ku[(k0 + tig) * 264 + n0 + g],
                                      Ku[(k0 + tig + 4) * 264 + n0 + g] };
                    mma_tf32(c[nt], a[ks], b);
                }
            }
        }

        // ---- prefetch next tile's Q (overlaps softmax + stores + AV) ----
        if (mq < 7) {
            const float* qrow = qb + (mq + 1) * 32 + mrow;
#pragma unroll
            for (int ks = 0; ks < 2; ks++) {
                int k0 = ks * 8;
                qn[ks * 4 + 0] = qrow[(k0 + tig) * 256 + g];
                qn[ks * 4 + 1] = qrow[(k0 + tig) * 256 + 8 + g];
                qn[ks * 4 + 2] = qrow[(k0 + tig + 4) * 256 + g];
                qn[ks * 4 + 3] = qrow[(k0 + tig + 4) * 256 + 8 + g];
            }
        }

        // ---- softmax (no max subtraction: |logit| <= ~0.03). rows rA, rB ----
        int rA = mrow + g, rB = mrow + 8 + g;
        {
            float sA = 0.f, sB = 0.f;
#pragma unroll
            for (int nt = 0; nt < 8; nt++) {
                c[nt][0] = __expf(c[nt][0]); c[nt][1] = __expf(c[nt][1]);
                c[nt][2] = __expf(c[nt][2]); c[nt][3] = __expf(c[nt][3]);
                sA += c[nt][0] + c[nt][1];
                sB += c[nt][2] + c[nt][3];
            }
            sA += __shfl_xor_sync(0xFFFFFFFFu, sA, 1);
            sA += __shfl_xor_sync(0xFFFFFFFFu, sA, 2);
            sB += __shfl_xor_sync(0xFFFFFFFFu, sB, 1);
            sB += __shfl_xor_sync(0xFFFFFFFFu, sB, 2);
            if (tig == 0) { REDS[rA * 4 + nq] = sA; REDS[rB * 4 + nq] = sB; }
        }
        __syncthreads();
        {
            float rinvA = 1.f / (REDS[rA * 4] + REDS[rA * 4 + 1] + REDS[rA * 4 + 2] + REDS[rA * 4 + 3]);
            float rinvB = 1.f / (REDS[rB * 4] + REDS[rB * 4 + 1] + REDS[rB * 4 + 2] + REDS[rB * 4 + 3]);
            float* oA = attn + ((size_t)((win * 8 + head) * 256 + m0 + rA)) * 256;
            float* oB = attn + ((size_t)((win * 8 + head) * 256 + m0 + rB)) * 256;
#pragma unroll
            for (int nt = 0; nt < 8; nt++) {
                int n0 = nq * 64 + nt * 8 + tig * 2;
                c[nt][0] *= rinvA; c[nt][1] *= rinvA;
                c[nt][2] *= rinvB; c[nt][3] *= rinvB;
                __stcs((float2*)&oA[n0], make_float2(c[nt][0], c[nt][1]));
                __stcs((float2*)&oB[n0], make_float2(c[nt][2], c[nt][3]));
            }
        }

        // ---- AV: P (regs, via C->A shuffle) x V (smem). O partial m16 x d16 ----
        {
            float o0[4] = {0.f, 0.f, 0.f, 0.f};   // d 0..7
            float o1[4] = {0.f, 0.f, 0.f, 0.f};   // d 8..15
#pragma unroll
            for (int nt = 0; nt < 8; nt++) {
                int k0 = nq * 64 + nt * 8;
                float x0 = __shfl_sync(0xFFFFFFFFu, c[nt][0], srcA);
                float x1 = __shfl_sync(0xFFFFFFFFu, c[nt][1], srcA);
                float x2 = __shfl_sync(0xFFFFFFFFu, c[nt][2], srcA);
                float x3 = __shfl_sync(0xFFFFFFFFu, c[nt][3], srcA);
                float y0 = __shfl_sync(0xFFFFFFFFu, c[nt][0], srcA + 2);
                float y1 = __shfl_sync(0xFFFFFFFFu, c[nt][1], srcA + 2);
                float y2 = __shfl_sync(0xFFFFFFFFu, c[nt][2], srcA + 2);
                float y3 = __shfl_sync(0xFFFFFFFFu, c[nt][3], srcA + 2);
                unsigned a[4];
                a[0] = f2tf32(par ? x1 : x0);
                a[1] = f2tf32(par ? x3 : x2);
                a[2] = f2tf32(par ? y1 : y0);
                a[3] = f2tf32(par ? y3 : y2);
                unsigned b0[2] = { Vu[g * 260 + k0 + tig], Vu[g * 260 + k0 + tig + 4] };
                mma_tf32(o0, a, b0);
                unsigned b1[2] = { Vu[(8 + g) * 260 + k0 + tig], Vu[(8 + g) * 260 + k0 + tig + 4] };
                mma_tf32(o1, a, b1);
            }
            *(float2*)&Os[nq * 576 + (mrow + g) * 18 + tig * 2]         = make_float2(o0[0], o0[1]);
            *(float2*)&Os[nq * 576 + (mrow + 8 + g) * 18 + tig * 2]     = make_float2(o0[2], o0[3]);
            *(float2*)&Os[nq * 576 + (mrow + g) * 18 + 8 + tig * 2]     = make_float2(o1[0], o1[1]);
            *(float2*)&Os[nq * 576 + (mrow + 8 + g) * 18 + 8 + tig * 2] = make_float2(o1[2], o1[3]);
        }
        __syncthreads();

        // ---- reduce 4 nq partials, write out_win [win][c][m] coalesced ----
        // (no trailing barrier: the next tile's REDS/Os writes are ordered by
        //  its own sum-barrier, which every thread reaches only after this read)
        {
            float* outw = g_q1;
#pragma unroll
            for (int i = 0; i < 2; i++) {
                int e = i * 256 + t;
                int m = e & 31, d = e >> 5;
                float s = Os[m * 18 + d] + Os[576 + m * 18 + d]
                        + Os[1152 + m * 18 + d] + Os[1728 + m * 18 + d];
                outw[((size_t)win * 128 + head * 16 + d) * 256 + m0 + m] = s;
            }
        }
    }
}

// =====================================================================================
// K4: window reverse for `out`: out_win [win][c][m] -> NCHW (unchanged)
// =====================================================================================
__global__ void k4_winrev(float* __restrict__ outp)
{
    __shared__ float s[16 * 272];
    int a = blockIdx.x;
    int c = blockIdx.y;
    int t = threadIdx.x;
    int g = t >> 4, bcol = t & 15;

    const float* outw = g_q1;
    for (int j = 0; j < 16; j++) {
        float v = outw[((size_t)(j * 16 + g) * 128 + c) * 256 + a * 16 + bcol];
        int col = bcol * 16 + g;
        s[j * 272 + col + (col >> 4)] = v;
    }
    __syncthreads();
    for (int j = 0; j < 16; j++) {
        int col = t;
        outp[(size_t)c * 65536 + (a * 16 + j) * 256 + t] = s[j * 272 + col + (col >> 4)];
    }
}

// =====================================================================================
extern "C" void kernel_launch(void* const* d_in, const int* in_sizes, int n_in,
                              void* d_out, int out_size)
{
    const float* lms   = (const float*)d_in[0];
    const float* pan   = (const float*)d_in[1];
    const float* gms   = (const float*)d_in[2];
    const float* gpan  = (const float*)d_in[3];
    const float* qw1   = (const float*)d_in[4];
    const float* qb1   = (const float*)d_in[5];
    const float* qw2   = (const float*)d_in[6];
    const float* qb2   = (const float*)d_in[7];
    const float* kvw1  = (const float*)d_in[8];
    const float* kvb1  = (const float*)d_in[9];
    const float* kvw2  = (const float*)d_in[10];
    const float* kvb2  = (const float*)d_in[11];

    float* attn = (float*)d_out;                   // (256, 8, 256, 256)
    float* outp = attn + 134217728;                // (1, 128, 256, 256)

    cudaFuncSetAttribute(k1_ln_conv1, cudaFuncAttributeMaxDynamicSharedMemorySize, 69632);
    cudaFuncSetAttribute(k3_attn_mma, cudaFuncAttributeMaxDynamicSharedMemorySize, 43328);

    k1_ln_conv1<<<512, 256, 69632>>>(lms, pan, gms, gpan, qw1, qb1, kvw1, kvb1);
    k2_dwconv_scatter<<<dim3(16, 384), 256>>>(qw2, qb2, kvw2, kvb2);
    k3_attn_mma<<<dim3(8, 256), 256, 43328>>>(attn);
    k4_winrev<<<dim3(16, 128), 256>>>(outp);
}

// round 13
// speedup vs baseline: 3.3539x; 1.1437x over previous
#include <cuda_runtime.h>
#include <cuda_fp16.h>
#include <math.h>

// ---------------- scratch (device globals; no allocations allowed) ----------------
__device__ float  g_q1[128u * 65536u];          // 32 MB : conv1 q output (NCHW), later out_win
__device__ float  g_kv1[256u * 65536u];         // 64 MB : conv1 kv output (NCHW)
__device__ float  g_qw[256u * 128u * 256u];     // 32 MB : q  in [win][c][m] (fp32)
__device__ __half g_kw16[256u * 128u * 256u];   // 16 MB : k  in [win][c][m] (fp16)
__device__ float  g_vw[256u * 128u * 256u];     // 32 MB : v  in [win][c][m] (fp32)

// =====================================================================================
// helpers
// =====================================================================================
__device__ __forceinline__ unsigned f2tf32(float f) {
    unsigned u;
    asm("cvt.rna.tf32.f32 %0, %1;" : "=r"(u) : "f"(f));
    return u;
}
__device__ __forceinline__ void mma_tf32(float c[4], const unsigned a[4], const unsigned b[2]) {
    asm volatile(
        "mma.sync.aligned.m16n8k8.row.col.f32.tf32.tf32.f32 "
        "{%0,%1,%2,%3},{%4,%5,%6,%7},{%8,%9},{%0,%1,%2,%3};"
        : "+f"(c[0]), "+f"(c[1]), "+f"(c[2]), "+f"(c[3])
        : "r"(a[0]), "r"(a[1]), "r"(a[2]), "r"(a[3]), "r"(b[0]), "r"(b[1]));
}
__device__ __forceinline__ void mma_f16(float c[4], const unsigned a[4], const unsigned b[2]) {
    asm volatile(
        "mma.sync.aligned.m16n8k16.row.col.f32.f16.f16.f32 "
        "{%0,%1,%2,%3},{%4,%5,%6,%7},{%8,%9},{%0,%1,%2,%3};"
        : "+f"(c[0]), "+f"(c[1]), "+f"(c[2]), "+f"(c[3])
        : "r"(a[0]), "r"(a[1]), "r"(a[2]), "r"(a[3]), "r"(b[0]), "r"(b[1]));
}
__device__ __forceinline__ unsigned h2u(__half2 h) { return *reinterpret_cast<unsigned*>(&h); }

// =====================================================================================
// K1: LN + 1x1 convs as tf32 tensor GEMM with x hi/lo compensation. (unchanged)
// =====================================================================================
__global__ void __launch_bounds__(256, 2) k1_ln_conv1(
    const float* __restrict__ lms, const float* __restrict__ pan,
    const float* __restrict__ gms, const float* __restrict__ gpan,
    const float* __restrict__ qw1, const float* __restrict__ qb1,
    const float* __restrict__ kvw1, const float* __restrict__ kvb1)
{
    extern __shared__ float sw[];
    unsigned* Xh = (unsigned*)sw;            // 64 x 136
    unsigned* Xl = (unsigned*)(sw + 8704);   // 64 x 136

    int t = threadIdx.x;
    int lane = t & 31, w = t >> 5;
    int g = lane >> 2, tig = lane & 3;
    int p0 = blockIdx.x * 128;

    unsigned a[3][4][4];
    float bias0[3], bias1[3];
#pragma unroll
    for (int j = 0; j < 3; j++) {
        int R = j * 128 + w * 16;
        const float* Wsrc = (j == 0) ? qw1 : kvw1;
        int r0 = (j == 0) ? R : (R - 128);
#pragma unroll
        for (int ks = 0; ks < 4; ks++) {
            int k0 = ks * 8;
            a[j][ks][0] = f2tf32(Wsrc[(r0 + g) * 32 + k0 + tig]);
            a[j][ks][1] = f2tf32(Wsrc[(r0 + 8 + g) * 32 + k0 + tig]);
            a[j][ks][2] = f2tf32(Wsrc[(r0 + g) * 32 + k0 + tig + 4]);
            a[j][ks][3] = f2tf32(Wsrc[(r0 + 8 + g) * 32 + k0 + tig + 4]);
        }
        const float* Bsrc = (j == 0) ? qb1 : kvb1;
        bias0[j] = Bsrc[r0 + g];
        bias1[j] = Bsrc[r0 + 8 + g];
    }

    {
        int which = t >> 7;
        int px = t & 127;
        const float* src = which ? lms : pan;
        const float* gg  = which ? gms : gpan;
        float x[32];
        float s = 0.f, s2 = 0.f;
#pragma unroll
        for (int i = 0; i < 32; i++) {
            float v = src[i * 65536 + p0 + px];
            x[i] = v; s += v; s2 += v * v;
        }
        float m = s * (1.f / 32.f);
        float var = s2 * (1.f / 32.f) - m * m;
        float r = rsqrtf(var + 1e-5f);
#pragma unroll
        for (int i = 0; i < 32; i++) {
            float xn = (x[i] - m) * r * gg[i];
            unsigned xh = f2tf32(xn);
            unsigned xl = f2tf32(xn - __uint_as_float(xh));
            int row = which * 32 + i;
            Xh[row * 136 + px] = xh;
            Xl[row * 136 + px] = xl;
        }
    }
    __syncthreads();

    for (int nt = 0; nt < 16; nt++) {
        int n0 = nt * 8;
#pragma unroll
        for (int j = 0; j < 3; j++) {
            int xrow = (j > 0) ? 32 : 0;
            float c[4] = {bias0[j], bias0[j], bias1[j], bias1[j]};
#pragma unroll
            for (int ks = 0; ks < 4; ks++) {
                int k0 = ks * 8;
                unsigned bh[2] = { Xh[(xrow + k0 + tig) * 136 + n0 + g],
                                   Xh[(xrow + k0 + tig + 4) * 136 + n0 + g] };
                mma_tf32(c, a[j][ks], bh);
                unsigned bl[2] = { Xl[(xrow + k0 + tig) * 136 + n0 + g],
                                   Xl[(xrow + k0 + tig + 4) * 136 + n0 + g] };
                mma_tf32(c, a[j][ks], bl);
            }
            int R = j * 128 + w * 16;
            int px = p0 + n0 + tig * 2;
            int row0 = R + g, row1 = R + 8 + g;
            float* d0 = (row0 < 128) ? (g_q1 + (size_t)row0 * 65536)
                                     : (g_kv1 + (size_t)(row0 - 128) * 65536);
            float* d1 = (row1 < 128) ? (g_q1 + (size_t)row1 * 65536)
                                     : (g_kv1 + (size_t)(row1 - 128) * 65536);
            *(float2*)&d0[px] = make_float2(c[0], c[1]);
            *(float2*)&d1[px] = make_float2(c[2], c[3]);
        }
    }
}

// =====================================================================================
// K2: depthwise 3x3 (SAME) + dilated-window scatter. K channel written fp16.
// =====================================================================================
#define SK18(r, c) ((r) * 272 + (c) + ((c) >> 4))

__global__ void k2_dwconv_scatter(const float* __restrict__ qw2, const float* __restrict__ qb2,
                                  const float* __restrict__ kvw2, const float* __restrict__ kvb2)
{
    __shared__ float s[18 * 272];
    int c = blockIdx.y;
    int a = blockIdx.x;
    int h0 = a * 16;
    int t = threadIdx.x;

    const float* src; const float* wsrc; const float* bsrc; int cw;
    float* dstf = 0; __half* dsth = 0; int dstc;
    if (c < 128) {
        src = g_q1 + (size_t)c * 65536; dstf = g_qw; dstc = c;
        wsrc = qw2; bsrc = qb2; cw = c;
    } else {
        int ck = c - 128;
        src = g_kv1 + (size_t)ck * 65536;
        wsrc = kvw2; bsrc = kvb2; cw = ck;
        if (ck < 128) { dsth = g_kw16; dstc = ck; }
        else          { dstf = g_vw;   dstc = ck - 128; }
    }

    float w9[9];
#pragma unroll
    for (int j = 0; j < 9; j++) w9[j] = wsrc[cw * 9 + j];
    float bias = bsrc[cw];

    for (int i = t; i < 18 * 256; i += 256) {
        int rr = i >> 8, ww = i & 255;
        int h = h0 - 1 + rr;
        float v = (h >= 0 && h < 256) ? src[h * 256 + ww] : 0.f;
        s[SK18(rr, ww)] = v;
    }
    __syncthreads();

    int g = t >> 4, bcol = t & 15;
    for (int j = 0; j < 16; j++) {
        int hh = j, wx = g;
        int wpix = bcol * 16 + wx;
        float acc = bias;
#pragma unroll
        for (int dy = 0; dy < 3; dy++) {
#pragma unroll
            for (int dx = 0; dx < 3; dx++) {
                int ww = wpix + dx - 1;
                float v = (ww >= 0 && ww < 256) ? s[SK18(hh + dy, ww)] : 0.f;
                acc += w9[dy * 3 + dx] * v;
            }
        }
        int win = hh * 16 + wx;
        size_t idx = ((size_t)win * 128 + dstc) * 256 + a * 16 + bcol;
        if (dsth) dsth[idx] = __float2half(acc);
        else      dstf[idx] = acc;
    }
}

// =====================================================================================
// K3: attention, one block per (head, win), 256 threads, fp16 m16n8k16 MMA.
//   - QK: K=16 per mma (8 mma/warp-tile); K staged fp16 as d-pairs (conflict-free).
//   - P C-frags pack DIRECTLY into fp16 A-frags (no shuffles).
//   - V staged hi/lo fp16 (vl = v - fp16(v)) -> AV error ~0; P fp16 eps ~5e-4.
//   - no max-subtraction; k-norm folded into Q A-frags; 2 barriers/tile.
//   smem u32: Kh2 8x264 | Vh 16x132 | Vl 16x132 | Os 2304f | REDS 128f | RN 16f
//   = 35136 B -> 3 CTAs/SM.
// =====================================================================================
__global__ void __launch_bounds__(256, 3) k3_attn_mma(float* __restrict__ attn)
{
    extern __shared__ float sm[];
    unsigned* Kh2 = (unsigned*)sm;              // 2112
    unsigned* Vh  = (unsigned*)sm + 2112;       // 2112
    unsigned* Vl  = (unsigned*)sm + 4224;       // 2112
    float* Os   = sm + 6336;                    // 2304 (4 nq x 32 x 18)
    float* REDS = sm + 8640;                    // 128 (also ssq scratch pre-loop)
    float* RN   = sm + 8768;                    // 16

    int t    = threadIdx.x;
    int lane = t & 31, wid = t >> 5;
    int g    = lane >> 2, tig = lane & 3;
    int head = blockIdx.x;
    int win  = blockIdx.y;

    const float*  qb = g_qw   + ((size_t)win * 128 + head * 16) * 256;
    const __half* kb = g_kw16 + ((size_t)win * 128 + head * 16) * 256;
    const float*  vb = g_vw   + ((size_t)win * 128 + head * 16) * 256;

    // ---- stage K (fp16 -> d-pair smem) + ssq partials ----
    {
        __half kh[16];
#pragma unroll
        for (int d = 0; d < 16; d++) kh[d] = kb[d * 256 + t];
#pragma unroll
        for (int d = 0; d < 16; d++) {
            float kv = __half2float(kh[d]);
            float ssq = kv * kv;
#pragma unroll
            for (int off = 16; off > 0; off >>= 1) ssq += __shfl_xor_sync(0xFFFFFFFFu, ssq, off);
            if (lane == 0) REDS[d * 8 + wid] = ssq;
        }
#pragma unroll
        for (int dp = 0; dp < 8; dp++) {
            __half2 p = __halves2half2(kh[2 * dp], kh[2 * dp + 1]);
            Kh2[dp * 264 + t] = h2u(p);
        }
    }
    // ---- stage V hi/lo (fp32 -> fp16 pair-of-tokens smem) ----
#pragma unroll
    for (int i = 0; i < 8; i++) {
        int d = 2 * i + (t >> 7);
        int j = t & 127;
        float2 v2 = *(const float2*)&vb[d * 256 + 2 * j];
        __half2 vh = __floats2half2_rn(v2.x, v2.y);
        float rx = v2.x - __low2float(vh);
        float ry = v2.y - __high2float(vh);
        __half2 vl = __floats2half2_rn(rx, ry);
        Vh[d * 132 + j] = h2u(vh);
        Vl[d * 132 + j] = h2u(vl);
    }
    __syncthreads();
    if (t < 16) {
        float s = 0.f;
#pragma unroll
        for (int j = 0; j < 8; j++) s += REDS[t * 8 + j];
        RN[t] = 1.f / fmaxf(sqrtf(s), 1e-12f);
    }
    __syncthreads();

    int mt = wid >> 2, nq = wid & 3;     // warp role, fixed across tiles
    int mrow = mt * 16;

    // k-norm scales for the fp16 A-frag d-columns {2tig, 2tig+1, 2tig+8, 2tig+9}
    float rn0 = RN[2 * tig], rn1 = RN[2 * tig + 1];
    float rn2 = RN[2 * tig + 8], rn3 = RN[2 * tig + 9];

    // ---- prefetch Q rows for tile 0 (d-set for fp16 A-frag) ----
    float qn[8];
    {
        const float* qrow = qb + mrow;
        qn[0] = qrow[(2 * tig) * 256 + g];
        qn[1] = qrow[(2 * tig + 1) * 256 + g];
        qn[2] = qrow[(2 * tig) * 256 + 8 + g];
        qn[3] = qrow[(2 * tig + 1) * 256 + 8 + g];
        qn[4] = qrow[(2 * tig + 8) * 256 + g];
        qn[5] = qrow[(2 * tig + 9) * 256 + g];
        qn[6] = qrow[(2 * tig + 8) * 256 + 8 + g];
        qn[7] = qrow[(2 * tig + 9) * 256 + 8 + g];
    }

    for (int mq = 0; mq < 8; mq++) {
        int m0 = mq * 32;

        // ---- QK: m16 x n64 per warp, ONE K=16 mma per ntile ----
        float c[8][4];
        {
            unsigned a[4];
            a[0] = h2u(__floats2half2_rn(qn[0] * rn0, qn[1] * rn1));  // row g,   cols 2tig,2tig+1
            a[1] = h2u(__floats2half2_rn(qn[2] * rn0, qn[3] * rn1));  // row g+8
            a[2] = h2u(__floats2half2_rn(qn[4] * rn2, qn[5] * rn3));  // row g,   cols +8
            a[3] = h2u(__floats2half2_rn(qn[6] * rn2, qn[7] * rn3));  // row g+8
#pragma unroll
            for (int nt = 0; nt < 8; nt++) {
                int n0 = nq * 64 + nt * 8;
                c[nt][0] = 0.f; c[nt][1] = 0.f; c[nt][2] = 0.f; c[nt][3] = 0.f;
                unsigned b[2] = { Kh2[tig * 264 + n0 + g],
                                  Kh2[(tig + 4) * 264 + n0 + g] };
                mma_f16(c[nt], a, b);
            }
        }

        // ---- prefetch next tile's Q (overlaps softmax + stores + AV) ----
        if (mq < 7) {
            const float* qrow = qb + (mq + 1) * 32 + mrow;
            qn[0] = qrow[(2 * tig) * 256 + g];
            qn[1] = qrow[(2 * tig + 1) * 256 + g];
            qn[2] = qrow[(2 * tig) * 256 + 8 + g];
            qn[3] = qrow[(2 * tig + 1) * 256 + 8 + g];
            qn[4] = qrow[(2 * tig + 8) * 256 + g];
            qn[5] = qrow[(2 * tig + 9) * 256 + g];
            qn[6] = qrow[(2 * tig + 8) * 256 + 8 + g];
            qn[7] = qrow[(2 * tig + 9) * 256 + 8 + g];
        }

        // ---- softmax (no max subtraction: logits tiny). rows rA, rB ----
        int rA = mrow + g, rB = mrow + 8 + g;
        {
            float sA = 0.f, sB = 0.f;
#pragma unroll
            for (int nt = 0; nt < 8; nt++) {
                c[nt][0] = __expf(c[nt][0]); c[nt][1] = __expf(c[nt][1]);
                c[nt][2] = __expf(c[nt][2]); c[nt][3] = __expf(c[nt][3]);
                sA += c[nt][0] + c[nt][1];
                sB += c[nt][2] + c[nt][3];
            }
            sA += __shfl_xor_sync(0xFFFFFFFFu, sA, 1);
            sA += __shfl_xor_sync(0xFFFFFFFFu, sA, 2);
            sB += __shfl_xor_sync(0xFFFFFFFFu, sB, 1);
            sB += __shfl_xor_sync(0xFFFFFFFFu, sB, 2);
            if (tig == 0) { REDS[rA * 4 + nq] = sA; REDS[rB * 4 + nq] = sB; }
        }
        __syncthreads();
        {
            float rinvA = 1.f / (REDS[rA * 4] + REDS[rA * 4 + 1] + REDS[rA * 4 + 2] + REDS[rA * 4 + 3]);
            float rinvB = 1.f / (REDS[rB * 4] + REDS[rB * 4 + 1] + REDS[rB * 4 + 2] + REDS[rB * 4 + 3]);
            float* oA = attn + ((size_t)((win * 8 + head) * 256 + m0 + rA)) * 256;
            float* oB = attn + ((size_t)((win * 8 + head) * 256 + m0 + rB)) * 256;
#pragma unroll
            for (int nt = 0; nt < 8; nt++) {
                int n0 = nq * 64 + nt * 8 + tig * 2;
                c[nt][0] *= rinvA; c[nt][1] *= rinvA;
                c[nt][2] *= rinvB; c[nt][3] *= rinvB;
                __stcs((float2*)&oA[n0], make_float2(c[nt][0], c[nt][1]));
                __stcs((float2*)&oB[n0], make_float2(c[nt][2], c[nt][3]));
            }
        }

        // ---- AV: P C-frags pack DIRECTLY into fp16 A-frags (no shuffles) ----
        {
            float o0[4] = {0.f, 0.f, 0.f, 0.f};   // d 0..7
            float o1[4] = {0.f, 0.f, 0.f, 0.f};   // d 8..15
#pragma unroll
            for (int u = 0; u < 4; u++) {
                int kp = nq * 32 + u * 8;          // token-pair base of this k16 chunk
                unsigned ah[4];
                ah[0] = h2u(__floats2half2_rn(c[2*u][0],   c[2*u][1]));
                ah[1] = h2u(__floats2half2_rn(c[2*u][2],   c[2*u][3]));
                ah[2] = h2u(__floats2half2_rn(c[2*u+1][0], c[2*u+1][1]));
                ah[3] = h2u(__floats2half2_rn(c[2*u+1][2], c[2*u+1][3]));
                unsigned bh0[2] = { Vh[g * 132 + kp + tig], Vh[g * 132 + kp + tig + 4] };
                mma_f16(o0, ah, bh0);
                unsigned bl0[2] = { Vl[g * 132 + kp + tig], Vl[g * 132 + kp + tig + 4] };
                mma_f16(o0, ah, bl0);
                unsigned bh1[2] = { Vh[(8 + g) * 132 + kp + tig], Vh[(8 + g) * 132 + kp + tig + 4] };
                mma_f16(o1, ah, bh1);
                unsigned bl1[2] = { Vl[(8 + g) * 132 + kp + tig], Vl[(8 + g) * 132 + kp + tig + 4] };
                mma_f16(o1, ah, bl1);
            }
            *(float2*)&Os[nq * 576 + (mrow + g) * 18 + tig * 2]         = make_float2(o0[0], o0[1]);
            *(float2*)&Os[nq * 576 + (mrow + 8 + g) * 18 + tig * 2]     = make_float2(o0[2], o0[3]);
            *(float2*)&Os[nq * 576 + (mrow + g) * 18 + 8 + tig * 2]     = make_float2(o1[0], o1[1]);
            *(float2*)&Os[nq * 576 + (mrow + 8 + g) * 18 + 8 + tig * 2] = make_float2(o1[2], o1[3]);
        }
        __syncthreads();

        // ---- reduce 4 nq partials, write out_win [win][c][m] coalesced ----
        // (no trailing barrier: next tile's REDS/Os writes are ordered by its own
        //  sum-barrier, which every thread reaches only after these reads)
        {
            float* outw = g_q1;
#pragma unroll
            for (int i = 0; i < 2; i++) {
                int e = i * 256 + t;
                int m = e & 31, d = e >> 5;
                float s = Os[m * 18 + d] + Os[576 + m * 18 + d]
                        + Os[1152 + m * 18 + d] + Os[1728 + m * 18 + d];
                outw[((size_t)win * 128 + head * 16 + d) * 256 + m0 + m] = s;
            }
        }
    }
}

// =====================================================================================
// K4: window reverse for `out`: out_win [win][c][m] -> NCHW (unchanged)
// =====================================================================================
__global__ void k4_winrev(float* __restrict__ outp)
{
    __shared__ float s[16 * 272];
    int a = blockIdx.x;
    int c = blockIdx.y;
    int t = threadIdx.x;
    int g = t >> 4, bcol = t & 15;

    const float* outw = g_q1;
    for (int j = 0; j < 16; j++) {
        float v = outw[((size_t)(j * 16 + g) * 128 + c) * 256 + a * 16 + bcol];
        int col = bcol * 16 + g;
        s[j * 272 + col + (col >> 4)] = v;
    }
    __syncthreads();
    for (int j = 0; j < 16; j++) {
        int col = t;
        outp[(size_t)c * 65536 + (a * 16 + j) * 256 + t] = s[j * 272 + col + (col >> 4)];
    }
}

// =====================================================================================
extern "C" void kernel_launch(void* const* d_in, const int* in_sizes, int n_in,
                              void* d_out, int out_size)
{
    const float* lms   = (const float*)d_in[0];
    const float* pan   = (const float*)d_in[1];
    const float* gms   = (const float*)d_in[2];
    const float* gpan  = (const float*)d_in[3];
    const float* qw1   = (const float*)d_in[4];
    const float* qb1   = (const float*)d_in[5];
    const float* qw2   = (const float*)d_in[6];
    const float* qb2   = (const float*)d_in[7];
    const float* kvw1  = (const float*)d_in[8];
    const float* kvb1  = (const float*)d_in[9];
    const float* kvw2  = (const float*)d_in[10];
    const float* kvb2  = (const float*)d_in[11];

    float* attn = (float*)d_out;                   // (256, 8, 256, 256)
    float* outp = attn + 134217728;                // (1, 128, 256, 256)

    cudaFuncSetAttribute(k1_ln_conv1, cudaFuncAttributeMaxDynamicSharedMemorySize, 69632);
    cudaFuncSetAttribute(k3_attn_mma, cudaFuncAttributeMaxDynamicSharedMemorySize, 35136);

    k1_ln_conv1<<<512, 256, 69632>>>(lms, pan, gms, gpan, qw1, qb1, kvw1, kvb1);
    k2_dwconv_scatter<<<dim3(16, 384), 256>>>(qw2, qb2, kvw2, kvb2);
    k3_attn_mma<<<dim3(8, 256), 256, 35136>>>(attn);
    k4_winrev<<<dim3(16, 128), 256>>>(outp);
}

// round 15
// speedup vs baseline: 3.3874x; 1.0100x over previous
#include <cuda_runtime.h>
#include <cuda_fp16.h>
#include <math.h>

// ---------------- scratch (device globals; no allocations allowed) ----------------
__device__ __half g_q1h[128u * 65536u];         // 16 MB : conv1 q out (NCHW, fp16)
__device__ __half g_k1h[128u * 65536u];         // 16 MB : conv1 k out (NCHW, fp16)
__device__ float  g_v1[128u * 65536u];          // 32 MB : conv1 v out (NCHW, fp32)
__device__ __half g_qw16[256u * 128u * 256u];   // 16 MB : q  [win][c][m] fp16
__device__ __half g_kw16[256u * 128u * 256u];   // 16 MB : k  [win][c][m] fp16
__device__ float  g_vw[256u * 128u * 256u];     // 32 MB : v  [win][c][m] fp32
__device__ float  g_outw[128u * 65536u];        // 32 MB : out_win [win][c][m]

// =====================================================================================
// helpers
// =====================================================================================
__device__ __forceinline__ unsigned f2tf32(float f) {
    unsigned u;
    asm("cvt.rna.tf32.f32 %0, %1;" : "=r"(u) : "f"(f));
    return u;
}
__device__ __forceinline__ void mma_tf32(float c[4], const unsigned a[4], const unsigned b[2]) {
    asm volatile(
        "mma.sync.aligned.m16n8k8.row.col.f32.tf32.tf32.f32 "
        "{%0,%1,%2,%3},{%4,%5,%6,%7},{%8,%9},{%0,%1,%2,%3};"
        : "+f"(c[0]), "+f"(c[1]), "+f"(c[2]), "+f"(c[3])
        : "r"(a[0]), "r"(a[1]), "r"(a[2]), "r"(a[3]), "r"(b[0]), "r"(b[1]));
}
__device__ __forceinline__ void mma_f16(float c[4], const unsigned a[4], const unsigned b[2]) {
    asm volatile(
        "mma.sync.aligned.m16n8k16.row.col.f32.f16.f16.f32 "
        "{%0,%1,%2,%3},{%4,%5,%6,%7},{%8,%9},{%0,%1,%2,%3};"
        : "+f"(c[0]), "+f"(c[1]), "+f"(c[2]), "+f"(c[3])
        : "r"(a[0]), "r"(a[1]), "r"(a[2]), "r"(a[3]), "r"(b[0]), "r"(b[1]));
}
__device__ __forceinline__ unsigned h2u(__half2 h) { return *reinterpret_cast<unsigned*>(&h); }

// =====================================================================================
// K1: LN + 1x1 convs as tf32 tensor GEMM with x hi/lo compensation.
//   q rows (0..127) and k rows (kv 0..127) stored fp16; v rows (kv 128..255) fp32.
// =====================================================================================
__global__ void __launch_bounds__(256, 2) k1_ln_conv1(
    const float* __restrict__ lms, const float* __restrict__ pan,
    const float* __restrict__ gms, const float* __restrict__ gpan,
    const float* __restrict__ qw1, const float* __restrict__ qb1,
    const float* __restrict__ kvw1, const float* __restrict__ kvb1)
{
    extern __shared__ float sw[];
    unsigned* Xh = (unsigned*)sw;            // 64 x 136
    unsigned* Xl = (unsigned*)(sw + 8704);   // 64 x 136

    int t = threadIdx.x;
    int lane = t & 31, w = t >> 5;
    int g = lane >> 2, tig = lane & 3;
    int p0 = blockIdx.x * 128;

    unsigned a[3][4][4];
    float bias0[3], bias1[3];
#pragma unroll
    for (int j = 0; j < 3; j++) {
        int R = j * 128 + w * 16;
        const float* Wsrc = (j == 0) ? qw1 : kvw1;
        int r0 = (j == 0) ? R : (R - 128);
#pragma unroll
        for (int ks = 0; ks < 4; ks++) {
            int k0 = ks * 8;
            a[j][ks][0] = f2tf32(Wsrc[(r0 + g) * 32 + k0 + tig]);
            a[j][ks][1] = f2tf32(Wsrc[(r0 + 8 + g) * 32 + k0 + tig]);
            a[j][ks][2] = f2tf32(Wsrc[(r0 + g) * 32 + k0 + tig + 4]);
            a[j][ks][3] = f2tf32(Wsrc[(r0 + 8 + g) * 32 + k0 + tig + 4]);
        }
        const float* Bsrc = (j == 0) ? qb1 : kvb1;
        bias0[j] = Bsrc[r0 + g];
        bias1[j] = Bsrc[r0 + 8 + g];
    }

    {
        int which = t >> 7;
        int px = t & 127;
        const float* src = which ? lms : pan;
        const float* gg  = which ? gms : gpan;
        float x[32];
        float s = 0.f, s2 = 0.f;
#pragma unroll
        for (int i = 0; i < 32; i++) {
            float v = src[i * 65536 + p0 + px];
            x[i] = v; s += v; s2 += v * v;
        }
        float m = s * (1.f / 32.f);
        float var = s2 * (1.f / 32.f) - m * m;
        float r = rsqrtf(var + 1e-5f);
#pragma unroll
        for (int i = 0; i < 32; i++) {
            float xn = (x[i] - m) * r * gg[i];
            unsigned xh = f2tf32(xn);
            unsigned xl = f2tf32(xn - __uint_as_float(xh));
            int row = which * 32 + i;
            Xh[row * 136 + px] = xh;
            Xl[row * 136 + px] = xl;
        }
    }
    __syncthreads();

    for (int nt = 0; nt < 16; nt++) {
        int n0 = nt * 8;
#pragma unroll
        for (int j = 0; j < 3; j++) {
            int xrow = (j > 0) ? 32 : 0;
            float c[4] = {bias0[j], bias0[j], bias1[j], bias1[j]};
#pragma unroll
            for (int ks = 0; ks < 4; ks++) {
                int k0 = ks * 8;
                unsigned bh[2] = { Xh[(xrow + k0 + tig) * 136 + n0 + g],
                                   Xh[(xrow + k0 + tig + 4) * 136 + n0 + g] };
                mma_tf32(c, a[j][ks], bh);
                unsigned bl[2] = { Xl[(xrow + k0 + tig) * 136 + n0 + g],
                                   Xl[(xrow + k0 + tig + 4) * 136 + n0 + g] };
                mma_tf32(c, a[j][ks], bl);
            }
            int r = w * 16 + g;                 // channel row within the 128-block
            size_t px = (size_t)(p0 + n0 + tig * 2);
            if (j == 0) {
                *(__half2*)&g_q1h[(size_t)r * 65536 + px]       = __floats2half2_rn(c[0], c[1]);
                *(__half2*)&g_q1h[(size_t)(r + 8) * 65536 + px] = __floats2half2_rn(c[2], c[3]);
            } else if (j == 1) {
                *(__half2*)&g_k1h[(size_t)r * 65536 + px]       = __floats2half2_rn(c[0], c[1]);
                *(__half2*)&g_k1h[(size_t)(r + 8) * 65536 + px] = __floats2half2_rn(c[2], c[3]);
            } else {
                *(float2*)&g_v1[(size_t)r * 65536 + px]         = make_float2(c[0], c[1]);
                *(float2*)&g_v1[(size_t)(r + 8) * 65536 + px]   = make_float2(c[2], c[3]);
            }
        }
    }
}

// =====================================================================================
// K2: depthwise 3x3 (SAME) + dilated-window scatter. q/k fp16 in+out, v fp32.
// =====================================================================================
#define SK18(r, c) ((r) * 272 + (c) + ((c) >> 4))

__global__ void k2_dwconv_scatter(const float* __restrict__ qw2, const float* __restrict__ qb2,
                                  const float* __restrict__ kvw2, const float* __restrict__ kvb2)
{
    __shared__ float s[18 * 272];
    int c = blockIdx.y;
    int a = blockIdx.x;
    int h0 = a * 16;
    int t = threadIdx.x;

    const __half* srcH = 0; const float* srcF = 0;
    const float* wsrc; const float* bsrc; int cw;
    float* dstf = 0; __half* dsth = 0; int dstc;
    if (c < 128) {
        srcH = g_q1h + (size_t)c * 65536; dsth = g_qw16; dstc = c;
        wsrc = qw2; bsrc = qb2; cw = c;
    } else {
        int ck = c - 128;
        wsrc = kvw2; bsrc = kvb2; cw = ck;
        if (ck < 128) { srcH = g_k1h + (size_t)ck * 65536; dsth = g_kw16; dstc = ck; }
        else          { srcF = g_v1 + (size_t)(ck - 128) * 65536; dstf = g_vw; dstc = ck - 128; }
    }

    float w9[9];
#pragma unroll
    for (int j = 0; j < 9; j++) w9[j] = wsrc[cw * 9 + j];
    float bias = bsrc[cw];

    for (int i = t; i < 18 * 256; i += 256) {
        int rr = i >> 8, ww = i & 255;
        int h = h0 - 1 + rr;
        float v = 0.f;
        if (h >= 0 && h < 256)
            v = srcH ? __half2float(srcH[h * 256 + ww]) : srcF[h * 256 + ww];
        s[SK18(rr, ww)] = v;
    }
    __syncthreads();

    int g = t >> 4, bcol = t & 15;
    for (int j = 0; j < 16; j++) {
        int hh = j, wx = g;
        int wpix = bcol * 16 + wx;
        float acc = bias;
#pragma unroll
        for (int dy = 0; dy < 3; dy++) {
#pragma unroll
            for (int dx = 0; dx < 3; dx++) {
                int ww = wpix + dx - 1;
                float v = (ww >= 0 && ww < 256) ? s[SK18(hh + dy, ww)] : 0.f;
                acc += w9[dy * 3 + dx] * v;
            }
        }
        int win = hh * 16 + wx;
        size_t idx = ((size_t)win * 128 + dstc) * 256 + a * 16 + bcol;
        if (dsth) dsth[idx] = __float2half(acc);
        else      dstf[idx] = acc;
    }
}

// =====================================================================================
// K3: attention, one block per (head, win), 256 threads, fp16 m16n8k16 MMA.
//   q read fp16 (new); k fp16; V hi/lo fp16; no-max softmax; 2 barriers/tile.
//   smem u32: Kh2 8x264 | Vh 16x132 | Vl 16x132 | Os 2304f | REDS 128f | RN 16f
// =====================================================================================
__global__ void __launch_bounds__(256, 3) k3_attn_mma(float* __restrict__ attn)
{
    extern __shared__ float sm[];
    unsigned* Kh2 = (unsigned*)sm;              // 2112
    unsigned* Vh  = (unsigned*)sm + 2112;       // 2112
    unsigned* Vl  = (unsigned*)sm + 4224;       // 2112
    float* Os   = sm + 6336;                    // 2304 (4 nq x 32 x 18)
    float* REDS = sm + 8640;                    // 128 (also ssq scratch pre-loop)
    float* RN   = sm + 8768;                    // 16

    int t    = threadIdx.x;
    int lane = t & 31, wid = t >> 5;
    int g    = lane >> 2, tig = lane & 3;
    int head = blockIdx.x;
    int win  = blockIdx.y;

    const __half* qb = g_qw16 + ((size_t)win * 128 + head * 16) * 256;
    const __half* kb = g_kw16 + ((size_t)win * 128 + head * 16) * 256;
    const float*  vb = g_vw   + ((size_t)win * 128 + head * 16) * 256;

    // ---- stage K (fp16 -> d-pair smem) + ssq partials ----
    {
        __half kh[16];
#pragma unroll
        for (int d = 0; d < 16; d++) kh[d] = kb[d * 256 + t];
#pragma unroll
        for (int d = 0; d < 16; d++) {
            float kv = __half2float(kh[d]);
            float ssq = kv * kv;
#pragma unroll
            for (int off = 16; off > 0; off >>= 1) ssq += __shfl_xor_sync(0xFFFFFFFFu, ssq, off);
            if (lane == 0) REDS[d * 8 + wid] = ssq;
        }
#pragma unroll
        for (int dp = 0; dp < 8; dp++) {
            __half2 p = __halves2half2(kh[2 * dp], kh[2 * dp + 1]);
            Kh2[dp * 264 + t] = h2u(p);
        }
    }
    // ---- stage V hi/lo (fp32 -> fp16 pair-of-tokens smem) ----
#pragma unroll
    for (int i = 0; i < 8; i++) {
        int d = 2 * i + (t >> 7);
        int j = t & 127;
        float2 v2 = *(const float2*)&vb[d * 256 + 2 * j];
        __half2 vh = __floats2half2_rn(v2.x, v2.y);
        float rx = v2.x - __low2float(vh);
        float ry = v2.y - __high2float(vh);
        __half2 vl = __floats2half2_rn(rx, ry);
        Vh[d * 132 + j] = h2u(vh);
        Vl[d * 132 + j] = h2u(vl);
    }
    __syncthreads();
    if (t < 16) {
        float s = 0.f;
#pragma unroll
        for (int j = 0; j < 8; j++) s += REDS[t * 8 + j];
        RN[t] = 1.f / fmaxf(sqrtf(s), 1e-12f);
    }
    __syncthreads();

    int mt = wid >> 2, nq = wid & 3;     // warp role, fixed across tiles
    int mrow = mt * 16;

    // k-norm scales for the fp16 A-frag d-columns {2tig, 2tig+1, 2tig+8, 2tig+9}
    float rn0 = RN[2 * tig], rn1 = RN[2 * tig + 1];
    float rn2 = RN[2 * tig + 8], rn3 = RN[2 * tig + 9];

    // ---- prefetch Q rows for tile 0 (fp16) ----
    float qn[8];
    {
        const __half* qrow = qb + mrow;
        qn[0] = __half2float(qrow[(2 * tig) * 256 + g]);
        qn[1] = __half2float(qrow[(2 * tig + 1) * 256 + g]);
        qn[2] = __half2float(qrow[(2 * tig) * 256 + 8 + g]);
        qn[3] = __half2float(qrow[(2 * tig + 1) * 256 + 8 + g]);
        qn[4] = __half2float(qrow[(2 * tig + 8) * 256 + g]);
        qn[5] = __half2float(qrow[(2 * tig + 9) * 256 + g]);
        qn[6] = __half2float(qrow[(2 * tig + 8) * 256 + 8 + g]);
        qn[7] = __half2float(qrow[(2 * tig + 9) * 256 + 8 + g]);
    }

    for (int mq = 0; mq < 8; mq++) {
        int m0 = mq * 32;

        // ---- QK: m16 x n64 per warp, ONE K=16 mma per ntile ----
        float c[8][4];
        {
            unsigned a[4];
            a[0] = h2u(__floats2half2_rn(qn[0] * rn0, qn[1] * rn1));
            a[1] = h2u(__floats2half2_rn(qn[2] * rn0, qn[3] * rn1));
            a[2] = h2u(__floats2half2_rn(qn[4] * rn2, qn[5] * rn3));
            a[3] = h2u(__floats2half2_rn(qn[6] * rn2, qn[7] * rn3));
#pragma unroll
            for (int nt = 0; nt < 8; nt++) {
                int n0 = nq * 64 + nt * 8;
                c[nt][0] = 0.f; c[nt][1] = 0.f; c[nt][2] = 0.f; c[nt][3] = 0.f;
                unsigned b[2] = { Kh2[tig * 264 + n0 + g],
                                  Kh2[(tig + 4) * 264 + n0 + g] };
                mma_f16(c[nt], a, b);
            }
        }

        // ---- prefetch next tile's Q (overlaps softmax + stores + AV) ----
        if (mq < 7) {
            const __half* qrow = qb + (mq + 1) * 32 + mrow;
            qn[0] = __half2float(qrow[(2 * tig) * 256 + g]);
            qn[1] = __half2float(qrow[(2 * tig + 1) * 256 + g]);
            qn[2] = __half2float(qrow[(2 * tig) * 256 + 8 + g]);
            qn[3] = __half2float(qrow[(2 * tig + 1) * 256 + 8 + g]);
            qn[4] = __half2float(qrow[(2 * tig + 8) * 256 + g]);
            qn[5] = __half2float(qrow[(2 * tig + 9) * 256 + g]);
            qn[6] = __half2float(qrow[(2 * tig + 8) * 256 + 8 + g]);
            qn[7] = __half2float(qrow[(2 * tig + 9) * 256 + 8 + g]);
        }

        // ---- softmax (no max subtraction: logits tiny). rows rA, rB ----
        int rA = mrow + g, rB = mrow + 8 + g;
        {
            float sA = 0.f, sB = 0.f;
#pragma unroll
            for (int nt = 0; nt < 8; nt++) {
                c[nt][0] = __expf(c[nt][0]); c[nt][1] = __expf(c[nt][1]);
                c[nt][2] = __expf(c[nt][2]); c[nt][3] = __expf(c[nt][3]);
                sA += c[nt][0] + c[nt][1];
                sB += c[nt][2] + c[nt][3];
            }
            sA += __shfl_xor_sync(0xFFFFFFFFu, sA, 1);
            sA += __shfl_xor_sync(0xFFFFFFFFu, sA, 2);
            sB += __shfl_xor_sync(0xFFFFFFFFu, sB, 1);
            sB += __shfl_xor_sync(0xFFFFFFFFu, sB, 2);
            if (tig == 0) { REDS[rA * 4 + nq] = sA; REDS[rB * 4 + nq] = sB; }
        }
        __syncthreads();
        {
            float rinvA = 1.f / (REDS[rA * 4] + REDS[rA * 4 + 1] + REDS[rA * 4 + 2] + REDS[rA * 4 + 3]);
            float rinvB = 1.f / (REDS[rB * 4] + REDS[rB * 4 + 1] + REDS[rB * 4 + 2] + REDS[rB * 4 + 3]);
            float* oA = attn + ((size_t)((win * 8 + head) * 256 + m0 + rA)) * 256;
            float* oB = attn + ((size_t)((win * 8 + head) * 256 + m0 + rB)) * 256;
#pragma unroll
            for (int nt = 0; nt < 8; nt++) {
                int n0 = nq * 64 + nt * 8 + tig * 2;
                c[nt][0] *= rinvA; c[nt][1] *= rinvA;
                c[nt][2] *= rinvB; c[nt][3] *= rinvB;
                __stcs((float2*)&oA[n0], make_float2(c[nt][0], c[nt][1]));
                __stcs((float2*)&oB[n0], make_float2(c[nt][2], c[nt][3]));
            }
        }

        // ---- AV: P C-frags pack DIRECTLY into fp16 A-frags (no shuffles) ----
        {
            float o0[4] = {0.f, 0.f, 0.f, 0.f};   // d 0..7
            float o1[4] = {0.f, 0.f, 0.f, 0.f};   // d 8..15
#pragma unroll
            for (int u = 0; u < 4; u++) {
                int kp = nq * 32 + u * 8;
                unsigned ah[4];
                ah[0] = h2u(__floats2half2_rn(c[2*u][0],   c[2*u][1]));
                ah[1] = h2u(__floats2half2_rn(c[2*u][2],   c[2*u][3]));
                ah[2] = h2u(__floats2half2_rn(c[2*u+1][0], c[2*u+1][1]));
                ah[3] = h2u(__floats2half2_rn(c[2*u+1][2], c[2*u+1][3]));
                unsigned bh0[2] = { Vh[g * 132 + kp + tig], Vh[g * 132 + kp + tig + 4] };
                mma_f16(o0, ah, bh0);
                unsigned bl0[2] = { Vl[g * 132 + kp + tig], Vl[g * 132 + kp + tig + 4] };
                mma_f16(o0, ah, bl0);
                unsigned bh1[2] = { Vh[(8 + g) * 132 + kp + tig], Vh[(8 + g) * 132 + kp + tig + 4] };
                mma_f16(o1, ah, bh1);
                unsigned bl1[2] = { Vl[(8 + g) * 132 + kp + tig], Vl[(8 + g) * 132 + kp + tig + 4] };
                mma_f16(o1, ah, bl1);
            }
            *(float2*)&Os[nq * 576 + (mrow + g) * 18 + tig * 2]         = make_float2(o0[0], o0[1]);
            *(float2*)&Os[nq * 576 + (mrow + 8 + g) * 18 + tig * 2]     = make_float2(o0[2], o0[3]);
            *(float2*)&Os[nq * 576 + (mrow + g) * 18 + 8 + tig * 2]     = make_float2(o1[0], o1[1]);
            *(float2*)&Os[nq * 576 + (mrow + 8 + g) * 18 + 8 + tig * 2] = make_float2(o1[2], o1[3]);
        }
        __syncthreads();

        // ---- reduce 4 nq partials, write out_win [win][c][m] coalesced ----
        {
            float* outw = g_outw;
#pragma unroll
            for (int i = 0; i < 2; i++) {
                int e = i * 256 + t;
                int m = e & 31, d = e >> 5;
                float s = Os[m * 18 + d] + Os[576 + m * 18 + d]
                        + Os[1152 + m * 18 + d] + Os[1728 + m * 18 + d];
                outw[((size_t)win * 128 + head * 16 + d) * 256 + m0 + m] = s;
            }
        }
    }
}

// =====================================================================================
// K4: window reverse for `out`: out_win [win][c][m] -> NCHW
// =====================================================================================
__global__ void k4_winrev(float* __restrict__ outp)
{
    __shared__ float s[16 * 272];
    int a = blockIdx.x;
    int c = blockIdx.y;
    int t = threadIdx.x;
    int g = t >> 4, bcol = t & 15;

    const float* outw = g_outw;
    for (int j = 0; j < 16; j++) {
        float v = outw[((size_t)(j * 16 + g) * 128 + c) * 256 + a * 16 + bcol];
        int col = bcol * 16 + g;
        s[j * 272 + col + (col >> 4)] = v;
    }
    __syncthreads();
    for (int j = 0; j < 16; j++) {
        int col = t;
        outp[(size_t)c * 65536 + (a * 16 + j) * 256 + t] = s[j * 272 + col + (col >> 4)];
    }
}

// =====================================================================================
extern "C" void kernel_launch(void* const* d_in, const int* in_sizes, int n_in,
                              void* d_out, int out_size)
{
    const float* lms   = (const float*)d_in[0];
    const float* pan   = (const float*)d_in[1];
    const float* gms   = (const float*)d_in[2];
    const float* gpan  = (const float*)d_in[3];
    const float* qw1   = (const float*)d_in[4];
    const float* qb1   = (const float*)d_in[5];
    const float* qw2   = (const float*)d_in[6];
    const float* qb2   = (const float*)d_in[7];
    const float* kvw1  = (const float*)d_in[8];
    const float* kvb1  = (const float*)d_in[9];
    const float* kvw2  = (const float*)d_in[10];
    const float* kvb2  = (const float*)d_in[11];

    float* attn = (float*)d_out;                   // (256, 8, 256, 256)
    float* outp = attn + 134217728;                // (1, 128, 256, 256)

    cudaFuncSetAttribute(k1_ln_conv1, cudaFuncAttributeMaxDynamicSharedMemorySize, 69632);
    cudaFuncSetAttribute(k3_attn_mma, cudaFuncAttributeMaxDynamicSharedMemorySize, 35136);

    k1_ln_conv1<<<512, 256, 69632>>>(lms, pan, gms, gpan, qw1, qb1, kvw1, kvb1);
    k2_dwconv_scatter<<<dim3(16, 384), 256>>>(qw2, qb2, kvw2, kvb2);
    k3_attn_mma<<<dim3(8, 256), 256, 35136>>>(attn);
    k4_winrev<<<dim3(16, 128), 256>>>(outp);
}